// round 1
// baseline (speedup 1.0000x reference)
#include <cuda_runtime.h>
#include <math.h>

#define Bn 8
#define Cc 64
#define Hh 128
#define Ww 128

// ---------------- device scratch (no allocs allowed) ----------------
__device__ float g_feat[Bn*Hh*Ww*Cc];      // NHWC feat          33.5 MB
__device__ float g_offmod[Bn*Hh*Ww*32];    // NHWC off(18)+mod(9) 16.8 MB
__device__ float g_w1t[128*64*9];          // [ic][oc][tap]
__device__ float g_w2t[64*32*9];           // [ic][oc(32 padded)][tap]
__device__ float g_wdcnt[9*64*64];         // [tap][oc][c]
__device__ float g_b2[32];                 // merged boff/bmod

// ---------------- weight transpose / merge ----------------
__global__ void prep_kernel(const float* __restrict__ W1,
                            const float* __restrict__ Woff,
                            const float* __restrict__ Wmod,
                            const float* __restrict__ Wdcn,
                            const float* __restrict__ boff,
                            const float* __restrict__ bmod)
{
    int i = blockIdx.x * blockDim.x + threadIdx.x;
    if (i < 128*64*9) {                       // W1 [oc=64][ic=128][3][3] -> [ic][oc][9]
        int ic = i / 576; int rem = i - ic*576;
        int oc = rem / 9; int t = rem - oc*9;
        g_w1t[i] = W1[(oc*128 + ic)*9 + t];
    }
    if (i < 64*32*9) {                        // Woff(18)+Wmod(9)+pad -> [ic=64][oc=32][9]
        int ic = i / 288; int rem = i - ic*288;
        int oc = rem / 9; int t = rem - oc*9;
        float v = 0.f;
        if (oc < 18)       v = Woff[(oc*64 + ic)*9 + t];
        else if (oc < 27)  v = Wmod[((oc-18)*64 + ic)*9 + t];
        g_w2t[i] = v;
    }
    if (i < 9*64*64) {                        // Wdcn [oc][c][9] -> [tap][oc][c]
        int k = i / 4096; int rem = i - k*4096;
        int oc = rem >> 6; int c = rem & 63;
        g_wdcnt[i] = Wdcn[(oc*64 + c)*9 + k];
    }
    if (i < 32) {
        g_b2[i] = (i < 18) ? boff[i] : (i < 27 ? bmod[i-18] : 0.f);
    }
}

// ---------------- generic fused 3x3 conv ----------------
// Tile: 8 rows x 32 cols of output pixels per block, all OC channels.
// Threads = (OC/OCPT)*32 : thread owns OCPT output channels x 8 x-pixels.
// MODE 0: input = concat(x_vq, x_res) NCHW, weights g_w1t, output -> g_feat NHWC
// MODE 1: input = g_feat NHWC,           weights g_w2t, output -> g_offmod NHWC (sigmoid on 18..26)
template<int IC, int OC, int OCPT, int MODE>
__global__ __launch_bounds__(256)
void conv3x3_kernel(const float* __restrict__ in0,
                    const float* __restrict__ in1,
                    const float* __restrict__ bias1)
{
    constexpr int OCG = OC / OCPT;      // 8
    constexpr int NT  = OCG * 32;       // 256
    constexpr int ICB = 4;
    constexpr int RS  = 35;             // padded smem row stride (10 rows x 34 cols used)

    __shared__ float sIn[ICB][10*RS];
    __shared__ float sW[ICB][OC*9];

    const float* __restrict__ wT   = (MODE == 0) ? g_w1t : g_w2t;
    const float* __restrict__ bias = (MODE == 0) ? bias1 : g_b2;

    const int tid  = threadIdx.x;
    const int b    = blockIdx.z;
    const int y0   = blockIdx.y << 3;
    const int x0   = blockIdx.x << 5;
    const int ocg  = tid >> 5;
    const int lane = tid & 31;
    const int r    = lane >> 2;
    const int xb   = (lane & 3) << 3;

    float acc[OCPT][8];
    #pragma unroll
    for (int j = 0; j < OCPT; j++) {
        float bv = bias[ocg*OCPT + j];
        #pragma unroll
        for (int p = 0; p < 8; p++) acc[j][p] = bv;
    }

    for (int ic0 = 0; ic0 < IC; ic0 += ICB) {
        __syncthreads();
        // load input patch (10 x 34) per ic of chunk
        for (int i = tid; i < ICB*340; i += NT) {
            int icL = i / 340; int rem = i - icL*340;
            int rr = rem / 34; int cc = rem - rr*34;
            int gy = y0 - 1 + rr, gx = x0 - 1 + cc;
            float v = 0.f;
            if ((unsigned)gy < (unsigned)Hh && (unsigned)gx < (unsigned)Ww) {
                int ic = ic0 + icL;
                if (MODE == 0) {
                    const float* src = (ic < 64) ? in0 : in1;
                    v = src[((b*64 + (ic & 63))*Hh + gy)*Ww + gx];
                } else {
                    v = g_feat[(((b*Hh + gy)*Ww + gx) << 6) + ic];
                }
            }
            sIn[icL][rr*RS + cc] = v;
        }
        // load weights (contiguous, coalesced)
        for (int i = tid; i < ICB*OC*9; i += NT) {
            int icL = i / (OC*9); int j = i - icL*(OC*9);
            sW[icL][j] = wT[(ic0 + icL)*(OC*9) + j];
        }
        __syncthreads();

        #pragma unroll
        for (int icL = 0; icL < ICB; icL++) {
            float vin[3][10];
            #pragma unroll
            for (int dy = 0; dy < 3; dy++)
                #pragma unroll
                for (int dx = 0; dx < 10; dx++)
                    vin[dy][dx] = sIn[icL][(r + dy)*RS + xb + dx];

            #pragma unroll
            for (int j = 0; j < OCPT; j++) {
                const float* w = &sW[icL][(ocg*OCPT + j)*9];
                float w0 = w[0], w1 = w[1], w2 = w[2];
                float w3 = w[3], w4 = w[4], w5 = w[5];
                float w6 = w[6], w7 = w[7], w8 = w[8];
                #pragma unroll
                for (int p = 0; p < 8; p++) {
                    float s = acc[j][p];
                    s += w0*vin[0][p]; s += w1*vin[0][p+1]; s += w2*vin[0][p+2];
                    s += w3*vin[1][p]; s += w4*vin[1][p+1]; s += w5*vin[1][p+2];
                    s += w6*vin[2][p]; s += w7*vin[2][p+1]; s += w8*vin[2][p+2];
                    acc[j][p] = s;
                }
            }
        }
    }

    const int y = y0 + r;
    #pragma unroll
    for (int j = 0; j < OCPT; j++) {
        int oc = ocg*OCPT + j;
        if (MODE == 1 && oc >= 27) continue;
        #pragma unroll
        for (int p = 0; p < 8; p++) {
            int x = x0 + xb + p;
            float v = acc[j][p];
            if (MODE == 0) {
                g_feat[(((b*Hh + y)*Ww + x) << 6) + oc] = v;
            } else {
                if (oc >= 18) v = 2.f / (1.f + expf(-v));
                g_offmod[(((b*Hh + y)*Ww + x) << 5) + oc] = v;
            }
        }
    }
}

// ---------------- deformable sampling + DCN GEMM ----------------
// Block: 8 rows x 16 cols = 128 pixels, all 64 oc. 256 threads.
// Loop over 9 taps: phase A bilinear-samples feat (mod folded) into sA[128][64],
// loads wdcn tap slice into sW[64][64]; phase B register-tiled GEMM 8px x 4oc.
#define AS 68   // padded strides
#define WS 68

__global__ __launch_bounds__(256, 2)
void dcn_kernel(const float* __restrict__ bdcn, float* __restrict__ out)
{
    extern __shared__ float dsm[];
    float* sA  = dsm;               // [128][AS]
    float* sWk = dsm + 128*AS;      // [64][WS]

    const int tid = threadIdx.x;
    const int b   = blockIdx.z;
    const int y0  = blockIdx.y << 3;
    const int x0  = blockIdx.x << 4;

    // phase A mapping: 2 threads per pixel (channel halves)
    const int pl    = tid >> 1;           // 0..127 raster (r*16 + c)
    const int chalf = (tid & 1) << 5;     // 0 or 32
    const int ar = pl >> 4, ac = pl & 15;
    const int ay = y0 + ar, ax = x0 + ac;
    const int ombase = (((b*Hh + ay)*Ww + ax) << 5);

    // phase B mapping: thread owns 8 consecutive x-pixels (one row) x 4 oc
    const int pxg    = tid >> 4;          // 0..15
    const int ocg    = tid & 15;          // 0..15
    const int plbase = ((pxg >> 1) << 4) + ((pxg & 1) << 3);

    float acc[8][4];
    #pragma unroll
    for (int i = 0; i < 8; i++)
        #pragma unroll
        for (int j = 0; j < 4; j++) acc[i][j] = 0.f;

    for (int k = 0; k < 9; k++) {
        __syncthreads();
        // load wdcn slice for this tap (coalesced)
        #pragma unroll 4
        for (int i = tid; i < 4096; i += 256) {
            int oc = i >> 6, c = i & 63;
            sWk[oc*WS + c] = g_wdcnt[(k << 12) + i];
        }
        // bilinear sample feat for this tap
        {
            float dy = g_offmod[ombase + 2*k];
            float dx = g_offmod[ombase + 2*k + 1];
            float m  = g_offmod[ombase + 18 + k];
            int ki = k/3 - 1, kj = k - (k/3)*3 - 1;
            float py = (float)(ay + ki) + dy;
            float px = (float)(ax + kj) + dx;
            float fy0 = floorf(py), fx0 = floorf(px);
            float wy = py - fy0, wx = px - fx0;
            int iy0 = (int)fy0, ix0 = (int)fx0;
            int iy1 = iy0 + 1,  ix1 = ix0 + 1;
            bool vy0 = (iy0 >= 0) && (iy0 < Hh);
            bool vy1 = (iy1 >= 0) && (iy1 < Hh);
            bool vx0 = (ix0 >= 0) && (ix0 < Ww);
            bool vx1 = (ix1 >= 0) && (ix1 < Ww);
            float w00 = m*(1.f-wy)*(1.f-wx)*((vy0 && vx0) ? 1.f : 0.f);
            float w01 = m*(1.f-wy)*wx      *((vy0 && vx1) ? 1.f : 0.f);
            float w10 = m*wy*(1.f-wx)      *((vy1 && vx0) ? 1.f : 0.f);
            float w11 = m*wy*wx            *((vy1 && vx1) ? 1.f : 0.f);
            int cy0 = min(max(iy0, 0), Hh-1), cx0 = min(max(ix0, 0), Ww-1);
            int cy1 = min(max(iy1, 0), Hh-1), cx1 = min(max(ix1, 0), Ww-1);
            const float4* p00 = (const float4*)&g_feat[(((b*Hh + cy0)*Ww + cx0) << 6) + chalf];
            const float4* p01 = (const float4*)&g_feat[(((b*Hh + cy0)*Ww + cx1) << 6) + chalf];
            const float4* p10 = (const float4*)&g_feat[(((b*Hh + cy1)*Ww + cx0) << 6) + chalf];
            const float4* p11 = (const float4*)&g_feat[(((b*Hh + cy1)*Ww + cx1) << 6) + chalf];
            float4* dst = (float4*)&sA[pl*AS + chalf];
            #pragma unroll
            for (int j = 0; j < 8; j++) {
                float4 c00 = p00[j], c01 = p01[j], c10 = p10[j], c11 = p11[j];
                float4 a;
                a.x = w00*c00.x + w01*c01.x + w10*c10.x + w11*c11.x;
                a.y = w00*c00.y + w01*c01.y + w10*c10.y + w11*c11.y;
                a.z = w00*c00.z + w01*c01.z + w10*c10.z + w11*c11.z;
                a.w = w00*c00.w + w01*c01.w + w10*c10.w + w11*c11.w;
                dst[j] = a;
            }
        }
        __syncthreads();

        // GEMM accumulate over 64 channels for this tap
        #pragma unroll
        for (int c = 0; c < 64; c += 4) {
            float4 wv[4];
            #pragma unroll
            for (int j = 0; j < 4; j++)
                wv[j] = *(const float4*)&sWk[(ocg*4 + j)*WS + c];
            #pragma unroll
            for (int i = 0; i < 8; i++) {
                float4 av = *(const float4*)&sA[(plbase + i)*AS + c];
                #pragma unroll
                for (int j = 0; j < 4; j++) {
                    acc[i][j] += av.x * wv[j].x;
                    acc[i][j] += av.y * wv[j].y;
                    acc[i][j] += av.z * wv[j].z;
                    acc[i][j] += av.w * wv[j].w;
                }
            }
        }
    }

    // write out NCHW
    const int rr = pxg >> 1;
    const int cb = (pxg & 1) << 3;
    const int oy = y0 + rr;
    #pragma unroll
    for (int j = 0; j < 4; j++) {
        int oc = ocg*4 + j;
        float bv = bdcn[oc];
        float* op = &out[((b*64 + oc)*Hh + oy)*Ww + x0 + cb];
        #pragma unroll
        for (int i = 0; i < 8; i++) op[i] = acc[i][j] + bv;
    }
}

// ---------------- launch ----------------
extern "C" void kernel_launch(void* const* d_in, const int* in_sizes, int n_in,
                              void* d_out, int out_size)
{
    const float* x_vq  = (const float*)d_in[0];
    const float* x_res = (const float*)d_in[1];
    const float* W1    = (const float*)d_in[2];
    const float* b1    = (const float*)d_in[3];
    const float* Woff  = (const float*)d_in[4];
    const float* boff  = (const float*)d_in[5];
    const float* Wmod  = (const float*)d_in[6];
    const float* bmod  = (const float*)d_in[7];
    const float* Wdcn  = (const float*)d_in[8];
    const float* bdcn  = (const float*)d_in[9];
    float* out = (float*)d_out;

    // weight transposes / merges (tiny)
    prep_kernel<<<(128*64*9 + 255)/256, 256>>>(W1, Woff, Wmod, Wdcn, boff, bmod);

    // conv1: concat(x_vq, x_res) -> feat (NHWC)
    {
        dim3 grid(Ww/32, Hh/8, Bn);
        conv3x3_kernel<128, 64, 8, 0><<<grid, 256>>>(x_vq, x_res, b1);
    }
    // conv2: feat -> offsets + mod (NHWC, padded to 32ch)
    {
        dim3 grid(Ww/32, Hh/8, Bn);
        conv3x3_kernel<64, 32, 4, 1><<<grid, 256>>>(nullptr, nullptr, nullptr);
    }
    // dcn: deformable sampling + einsum
    {
        static const int smem_bytes = (128*AS + 64*WS) * (int)sizeof(float);
        cudaFuncSetAttribute(dcn_kernel, cudaFuncAttributeMaxDynamicSharedMemorySize, smem_bytes);
        dim3 grid(Ww/16, Hh/8, Bn);
        dcn_kernel<<<grid, 256, smem_bytes>>>(bdcn, out);
    }
}

// round 2
// speedup vs baseline: 1.2341x; 1.2341x over previous
#include <cuda_runtime.h>
#include <math.h>

#define Bn 8
#define Hh 128
#define Ww 128

// ---------------- device scratch ----------------
__device__ float g_feat[Bn*Hh*Ww*64];      // NHWC feat
__device__ float g_offmod[Bn*Hh*Ww*32];    // NHWC off(18)+mod(9)
__device__ float g_w1t[128*64*12];         // [ic][oc][tap12]
__device__ float g_w2t[64*32*12];          // [ic][oc32][tap12]
__device__ float g_wdcnt[9*64*64];         // [tap][c][oc]
__device__ float g_b2[32];

// ---------------- weight transpose / merge ----------------
__global__ void prep_kernel(const float* __restrict__ W1,
                            const float* __restrict__ Woff,
                            const float* __restrict__ Wmod,
                            const float* __restrict__ Wdcn,
                            const float* __restrict__ boff,
                            const float* __restrict__ bmod)
{
    int i = blockIdx.x * blockDim.x + threadIdx.x;
    if (i < 128*64*12) {                 // W1 [oc][ic][9] -> [ic][oc][12]
        int ic = i / 768; int rem = i - ic*768;
        int oc = rem / 12; int t = rem - oc*12;
        g_w1t[i] = (t < 9) ? W1[(oc*128 + ic)*9 + t] : 0.f;
    }
    if (i < 64*32*12) {                  // Woff(18)+Wmod(9)+pad -> [ic][oc32][12]
        int ic = i / 384; int rem = i - ic*384;
        int oc = rem / 12; int t = rem - oc*12;
        float v = 0.f;
        if (t < 9) {
            if (oc < 18)      v = Woff[(oc*64 + ic)*9 + t];
            else if (oc < 27) v = Wmod[((oc-18)*64 + ic)*9 + t];
        }
        g_w2t[i] = v;
    }
    if (i < 9*64*64) {                   // Wdcn [oc][c][9] -> [tap][c][oc]
        int k = i >> 12;
        int c = (i >> 6) & 63;
        int oc = i & 63;
        g_wdcnt[i] = Wdcn[(oc*64 + c)*9 + k];
    }
    if (i < 32) g_b2[i] = (i < 18) ? boff[i] : (i < 27 ? bmod[i-18] : 0.f);
}

// ---------------- generic fused 3x3 conv ----------------
// Tile: 8 rows x 32 cols, all OC. 256 threads; thread = OCPT oc x 8 px.
template<int IC, int OC, int OCPT, int MODE>
__global__ __launch_bounds__(256)
void conv3x3_kernel(const float* __restrict__ in0,
                    const float* __restrict__ in1,
                    const float* __restrict__ bias1)
{
    constexpr int OCG = OC / OCPT;
    constexpr int NT  = OCG * 32;      // 256
    constexpr int ICB = 4;
    constexpr int RS  = 36;            // padded smem row stride

    __shared__ float sIn[ICB][10*RS];
    __shared__ float sW[ICB][OC*12];

    const float* __restrict__ wT   = (MODE == 0) ? g_w1t : g_w2t;
    const float* __restrict__ bias = (MODE == 0) ? bias1 : g_b2;

    const int tid  = threadIdx.x;
    const int b    = blockIdx.z;
    const int y0   = blockIdx.y << 3;
    const int x0   = blockIdx.x << 5;
    const int ocg  = tid >> 5;
    const int lane = tid & 31;
    const int r    = lane >> 2;
    const int xb   = (lane & 3) << 3;

    float acc[OCPT][8];
    #pragma unroll
    for (int j = 0; j < OCPT; j++) {
        float bv = bias[ocg*OCPT + j];
        #pragma unroll
        for (int p = 0; p < 8; p++) acc[j][p] = bv;
    }

    for (int ic0 = 0; ic0 < IC; ic0 += ICB) {
        __syncthreads();
        for (int i = tid; i < ICB*340; i += NT) {
            int icL = i / 340; int rem = i - icL*340;
            int rr = rem / 34; int cc = rem - rr*34;
            int gy = y0 - 1 + rr, gx = x0 - 1 + cc;
            float v = 0.f;
            if ((unsigned)gy < (unsigned)Hh && (unsigned)gx < (unsigned)Ww) {
                int ic = ic0 + icL;
                if (MODE == 0) {
                    const float* src = (ic < 64) ? in0 : in1;
                    v = src[((b*64 + (ic & 63))*Hh + gy)*Ww + gx];
                } else {
                    v = g_feat[(((b*Hh + gy)*Ww + gx) << 6) + ic];
                }
            }
            sIn[icL][rr*RS + cc] = v;
        }
        for (int i = tid; i < ICB*OC*12; i += NT) {
            int icL = i / (OC*12); int j = i - icL*(OC*12);
            sW[icL][j] = wT[(ic0 + icL)*(OC*12) + j];
        }
        __syncthreads();

        #pragma unroll
        for (int icL = 0; icL < ICB; icL++) {
            float vin[3][10];
            #pragma unroll
            for (int dy = 0; dy < 3; dy++) {
                int base = (r + dy)*RS + xb;
                float4 a4 = *(const float4*)&sIn[icL][base];
                float4 b4 = *(const float4*)&sIn[icL][base + 4];
                vin[dy][0]=a4.x; vin[dy][1]=a4.y; vin[dy][2]=a4.z; vin[dy][3]=a4.w;
                vin[dy][4]=b4.x; vin[dy][5]=b4.y; vin[dy][6]=b4.z; vin[dy][7]=b4.w;
                vin[dy][8]=sIn[icL][base + 8];
                vin[dy][9]=sIn[icL][base + 9];
            }

            #pragma unroll
            for (int j = 0; j < OCPT; j++) {
                const float4* w4 = (const float4*)&sW[icL][(ocg*OCPT + j)*12];
                float4 wA = w4[0], wB = w4[1];
                float  w8 = sW[icL][(ocg*OCPT + j)*12 + 8];
                #pragma unroll
                for (int p = 0; p < 8; p++) {
                    float s = acc[j][p];
                    s += wA.x*vin[0][p]; s += wA.y*vin[0][p+1]; s += wA.z*vin[0][p+2];
                    s += wA.w*vin[1][p]; s += wB.x*vin[1][p+1]; s += wB.y*vin[1][p+2];
                    s += wB.z*vin[2][p]; s += wB.w*vin[2][p+1]; s += w8  *vin[2][p+2];
                    acc[j][p] = s;
                }
            }
        }
    }

    const int y = y0 + r;
    #pragma unroll
    for (int j = 0; j < OCPT; j++) {
        int oc = ocg*OCPT + j;
        if (MODE == 1 && oc >= 27) continue;
        #pragma unroll
        for (int p = 0; p < 8; p++) {
            int x = x0 + xb + p;
            float v = acc[j][p];
            if (MODE == 0) {
                g_feat[(((b*Hh + y)*Ww + x) << 6) + oc] = v;
            } else {
                if (oc >= 18) v = 2.f / (1.f + expf(-v));
                g_offmod[(((b*Hh + y)*Ww + x) << 5) + oc] = v;
            }
        }
    }
}

// ---------------- deformable sampling + DCN GEMM (smem-staged) ----------------
// Block: 16x16 px tile, 64 oc, 256 threads.
// sF: staged feat window 22x22 (halo ±3), ch stride 68.  sA: sampled [256 px][72].
// sW: [c][oc] tap slice. Thread = 8 px (stride 32) x 8 oc.
#define FW 22
#define FST 68
#define AST 72

__global__ __launch_bounds__(256, 1)
void dcn_kernel(const float* __restrict__ bdcn, float* __restrict__ out)
{
    extern __shared__ float sm[];
    float* sF = sm;                         // 22*22*68 = 32912 floats
    float* sA = sm + FW*FW*FST;             // 256*72   = 18432
    float* sW = sA + 256*AST;               // 64*64    = 4096

    const int tid = threadIdx.x;
    const int b   = blockIdx.z;
    const int y0  = blockIdx.y << 4;
    const int x0  = blockIdx.x << 4;

    // ---- stage feat window (zero-filled outside image) ----
    for (int i = tid; i < FW*FW*16; i += 256) {
        int px = i >> 4, cs = (i & 15) << 2;
        int row = px / FW, col = px - row*FW;
        int gy = y0 - 3 + row, gx = x0 - 3 + col;
        float4 v = make_float4(0.f, 0.f, 0.f, 0.f);
        if ((unsigned)gy < (unsigned)Hh && (unsigned)gx < (unsigned)Ww)
            v = *(const float4*)&g_feat[(((b*Hh + gy)*Ww + gx) << 6) + cs];
        *(float4*)&sF[px*FST + cs] = v;
    }

    // sampling role: thread = pixel tid
    const int ar = tid >> 4, ac = tid & 15;
    const int ay = y0 + ar, ax = x0 + ac;
    const float* __restrict__ omp = &g_offmod[(((b*Hh + ay)*Ww + ax)) << 5];

    // GEMM role
    const int pxg = tid >> 3;       // 0..31
    const int ocg = tid & 7;        // 0..7

    float acc[8][8];
    #pragma unroll
    for (int i = 0; i < 8; i++)
        #pragma unroll
        for (int j = 0; j < 8; j++) acc[i][j] = 0.f;

    __syncthreads();

    for (int k = 0; k < 9; k++) {
        // load wdcn tap slice [c][oc] (coalesced)
        #pragma unroll 4
        for (int i = tid; i < 4096; i += 256) sW[i] = g_wdcnt[(k << 12) + i];

        // ---- bilinear sample into sA ----
        {
            float dy = omp[2*k], dxo = omp[2*k + 1], m = omp[18 + k];
            int ki = k/3 - 1, kj = k - (k/3)*3 - 1;
            float py  = (float)(ay + ki) + dy;
            float pxf = (float)(ax + kj) + dxo;
            float fy = floorf(py), fx = floorf(pxf);
            float wy = py - fy, wx = pxf - fx;
            int iy0 = (int)fy, ix0 = (int)fx;
            float w00 = m*(1.f-wy)*(1.f-wx), w01 = m*(1.f-wy)*wx;
            float w10 = m*wy*(1.f-wx),       w11 = m*wy*wx;
            float* dst = &sA[tid*AST];
            int ry = iy0 - y0 + 3, rx = ix0 - x0 + 3;
            if ((unsigned)ry <= (unsigned)(FW-2) && (unsigned)rx <= (unsigned)(FW-2)) {
                // fast path: all 4 corners staged (zeros already model padding)
                const float* base = &sF[(ry*FW + rx)*FST];
                const float4* q00 = (const float4*)base;
                const float4* q01 = (const float4*)(base + FST);
                const float4* q10 = (const float4*)(base + FW*FST);
                const float4* q11 = (const float4*)(base + FW*FST + FST);
                #pragma unroll
                for (int j = 0; j < 16; j++) {
                    float4 c00 = q00[j], c01 = q01[j], c10 = q10[j], c11 = q11[j];
                    float4 rv;
                    rv.x = w00*c00.x + w01*c01.x + w10*c10.x + w11*c11.x;
                    rv.y = w00*c00.y + w01*c01.y + w10*c10.y + w11*c11.y;
                    rv.z = w00*c00.z + w01*c01.z + w10*c10.z + w11*c11.z;
                    rv.w = w00*c00.w + w01*c01.w + w10*c10.w + w11*c11.w;
                    *(float4*)&dst[4*j] = rv;
                }
            } else {
                // slow path: global gather with validity masks
                int iy1 = iy0 + 1, ix1 = ix0 + 1;
                bool vy0 = (iy0 >= 0) && (iy0 < Hh);
                bool vy1 = (iy1 >= 0) && (iy1 < Hh);
                bool vx0 = (ix0 >= 0) && (ix0 < Ww);
                bool vx1 = (ix1 >= 0) && (ix1 < Ww);
                float m00 = w00 * ((vy0 && vx0) ? 1.f : 0.f);
                float m01 = w01 * ((vy0 && vx1) ? 1.f : 0.f);
                float m10 = w10 * ((vy1 && vx0) ? 1.f : 0.f);
                float m11 = w11 * ((vy1 && vx1) ? 1.f : 0.f);
                int cy0 = min(max(iy0, 0), Hh-1), cx0 = min(max(ix0, 0), Ww-1);
                int cy1 = min(max(iy1, 0), Hh-1), cx1 = min(max(ix1, 0), Ww-1);
                const float4* p00 = (const float4*)&g_feat[(((b*Hh + cy0)*Ww + cx0) << 6)];
                const float4* p01 = (const float4*)&g_feat[(((b*Hh + cy0)*Ww + cx1) << 6)];
                const float4* p10 = (const float4*)&g_feat[(((b*Hh + cy1)*Ww + cx0) << 6)];
                const float4* p11 = (const float4*)&g_feat[(((b*Hh + cy1)*Ww + cx1) << 6)];
                #pragma unroll
                for (int j = 0; j < 16; j++) {
                    float4 c00 = p00[j], c01 = p01[j], c10 = p10[j], c11 = p11[j];
                    float4 rv;
                    rv.x = m00*c00.x + m01*c01.x + m10*c10.x + m11*c11.x;
                    rv.y = m00*c00.y + m01*c01.y + m10*c10.y + m11*c11.y;
                    rv.z = m00*c00.z + m01*c01.z + m10*c10.z + m11*c11.z;
                    rv.w = m00*c00.w + m01*c01.w + m10*c10.w + m11*c11.w;
                    *(float4*)&dst[4*j] = rv;
                }
            }
        }
        __syncthreads();

        // ---- GEMM: acc[8px][8oc] += sA * sW over 64 channels ----
        #pragma unroll 2
        for (int c0 = 0; c0 < 64; c0 += 4) {
            float4 av[8];
            #pragma unroll
            for (int i = 0; i < 8; i++)
                av[i] = *(const float4*)&sA[(pxg + 32*i)*AST + c0];
            #pragma unroll
            for (int cc = 0; cc < 4; cc++) {
                float4 wl = *(const float4*)&sW[(c0 + cc)*64 + ocg*8];
                float4 wh = *(const float4*)&sW[(c0 + cc)*64 + ocg*8 + 4];
                #pragma unroll
                for (int i = 0; i < 8; i++) {
                    float a = (cc == 0) ? av[i].x : (cc == 1) ? av[i].y
                            : (cc == 2) ? av[i].z : av[i].w;
                    acc[i][0] += a*wl.x; acc[i][1] += a*wl.y;
                    acc[i][2] += a*wl.z; acc[i][3] += a*wl.w;
                    acc[i][4] += a*wh.x; acc[i][5] += a*wh.y;
                    acc[i][6] += a*wh.z; acc[i][7] += a*wh.w;
                }
            }
        }
        __syncthreads();
    }

    // ---- epilogue: NCHW output ----
    #pragma unroll
    for (int j = 0; j < 8; j++) {
        int oc = ocg*8 + j;
        float bv = bdcn[oc];
        #pragma unroll
        for (int i = 0; i < 8; i++) {
            int p = pxg + 32*i;
            int row = p >> 4, col = p & 15;
            out[((b*64 + oc)*Hh + y0 + row)*Ww + x0 + col] = acc[i][j] + bv;
        }
    }
}

// ---------------- launch ----------------
extern "C" void kernel_launch(void* const* d_in, const int* in_sizes, int n_in,
                              void* d_out, int out_size)
{
    const float* x_vq  = (const float*)d_in[0];
    const float* x_res = (const float*)d_in[1];
    const float* W1    = (const float*)d_in[2];
    const float* b1    = (const float*)d_in[3];
    const float* Woff  = (const float*)d_in[4];
    const float* boff  = (const float*)d_in[5];
    const float* Wmod  = (const float*)d_in[6];
    const float* bmod  = (const float*)d_in[7];
    const float* Wdcn  = (const float*)d_in[8];
    const float* bdcn  = (const float*)d_in[9];
    float* out = (float*)d_out;

    prep_kernel<<<(128*64*12 + 255)/256, 256>>>(W1, Woff, Wmod, Wdcn, boff, bmod);

    {
        dim3 grid(Ww/32, Hh/8, Bn);
        conv3x3_kernel<128, 64, 8, 0><<<grid, 256>>>(x_vq, x_res, b1);
    }
    {
        dim3 grid(Ww/32, Hh/8, Bn);
        conv3x3_kernel<64, 32, 4, 1><<<grid, 256>>>(nullptr, nullptr, nullptr);
    }
    {
        const int smem_bytes = (FW*FW*FST + 256*AST + 64*64) * (int)sizeof(float);
        cudaFuncSetAttribute(dcn_kernel, cudaFuncAttributeMaxDynamicSharedMemorySize, smem_bytes);
        dim3 grid(Ww/16, Hh/16, Bn);
        dcn_kernel<<<grid, 256, smem_bytes>>>(bdcn, out);
    }
}

// round 4
// speedup vs baseline: 1.2347x; 1.0005x over previous
#include <cuda_runtime.h>
#include <math.h>

#define Bn 8
#define Hh 128
#define Ww 128

// ---------------- device scratch ----------------
__device__ float g_feat[Bn*Hh*Ww*64];      // NHWC feat
__device__ float g_offmod[Bn*Hh*Ww*32];    // NHWC off(18)+mod(9)
__device__ float g_w1t[128*64*12];         // [ic][oc][tap12]
__device__ float g_w2t[64*32*12];          // [ic][oc32][tap12]
__device__ float g_wdcnt[9*64*64];         // [tap][c][oc]
__device__ float g_b2[32];

// ---------------- weight transpose / merge ----------------
__global__ void prep_kernel(const float* __restrict__ W1,
                            const float* __restrict__ Woff,
                            const float* __restrict__ Wmod,
                            const float* __restrict__ Wdcn,
                            const float* __restrict__ boff,
                            const float* __restrict__ bmod)
{
    int i = blockIdx.x * blockDim.x + threadIdx.x;
    if (i < 128*64*12) {                 // W1 [oc][ic][9] -> [ic][oc][12]
        int ic = i / 768; int rem = i - ic*768;
        int oc = rem / 12; int t = rem - oc*12;
        g_w1t[i] = (t < 9) ? W1[(oc*128 + ic)*9 + t] : 0.f;
    }
    if (i < 64*32*12) {                  // Woff(18)+Wmod(9)+pad -> [ic][oc32][12]
        int ic = i / 384; int rem = i - ic*384;
        int oc = rem / 12; int t = rem - oc*12;
        float v = 0.f;
        if (t < 9) {
            if (oc < 18)      v = Woff[(oc*64 + ic)*9 + t];
            else if (oc < 27) v = Wmod[((oc-18)*64 + ic)*9 + t];
        }
        g_w2t[i] = v;
    }
    if (i < 9*64*64) {                   // Wdcn [oc][c][9] -> [tap][c][oc]
        int k = i >> 12;
        int c = (i >> 6) & 63;
        int oc = i & 63;
        g_wdcnt[i] = Wdcn[(oc*64 + c)*9 + k];
    }
    if (i < 32) g_b2[i] = (i < 18) ? boff[i] : (i < 27 ? bmod[i-18] : 0.f);
}

// ---------------- generic fused 3x3 conv ----------------
// Tile: 8 rows x 32 cols, all OC. 256 threads; thread = OCPT oc x 8 px.
template<int IC, int OC, int OCPT, int MODE>
__global__ __launch_bounds__(256)
void conv3x3_kernel(const float* __restrict__ in0,
                    const float* __restrict__ in1,
                    const float* __restrict__ bias1)
{
    constexpr int OCG = OC / OCPT;
    constexpr int NT  = OCG * 32;      // 256
    constexpr int ICB = 4;
    constexpr int RS  = 36;            // padded smem row stride

    __shared__ float sIn[ICB][10*RS];
    __shared__ float sW[ICB][OC*12];

    const float* __restrict__ wT   = (MODE == 0) ? g_w1t : g_w2t;
    const float* __restrict__ bias = (MODE == 0) ? bias1 : g_b2;

    const int tid  = threadIdx.x;
    const int b    = blockIdx.z;
    const int y0   = blockIdx.y << 3;
    const int x0   = blockIdx.x << 5;
    const int ocg  = tid >> 5;
    const int lane = tid & 31;
    const int r    = lane >> 2;
    const int xb   = (lane & 3) << 3;

    float acc[OCPT][8];
    #pragma unroll
    for (int j = 0; j < OCPT; j++) {
        float bv = bias[ocg*OCPT + j];
        #pragma unroll
        for (int p = 0; p < 8; p++) acc[j][p] = bv;
    }

    for (int ic0 = 0; ic0 < IC; ic0 += ICB) {
        __syncthreads();
        for (int i = tid; i < ICB*340; i += NT) {
            int icL = i / 340; int rem = i - icL*340;
            int rr = rem / 34; int cc = rem - rr*34;
            int gy = y0 - 1 + rr, gx = x0 - 1 + cc;
            float v = 0.f;
            if ((unsigned)gy < (unsigned)Hh && (unsigned)gx < (unsigned)Ww) {
                int ic = ic0 + icL;
                if (MODE == 0) {
                    const float* src = (ic < 64) ? in0 : in1;
                    v = src[((b*64 + (ic & 63))*Hh + gy)*Ww + gx];
                } else {
                    v = g_feat[(((b*Hh + gy)*Ww + gx) << 6) + ic];
                }
            }
            sIn[icL][rr*RS + cc] = v;
        }
        for (int i = tid; i < ICB*OC*12; i += NT) {
            int icL = i / (OC*12); int j = i - icL*(OC*12);
            sW[icL][j] = wT[(ic0 + icL)*(OC*12) + j];
        }
        __syncthreads();

        #pragma unroll
        for (int icL = 0; icL < ICB; icL++) {
            float vin[3][10];
            #pragma unroll
            for (int dy = 0; dy < 3; dy++) {
                int base = (r + dy)*RS + xb;
                float4 a4 = *(const float4*)&sIn[icL][base];
                float4 b4 = *(const float4*)&sIn[icL][base + 4];
                vin[dy][0]=a4.x; vin[dy][1]=a4.y; vin[dy][2]=a4.z; vin[dy][3]=a4.w;
                vin[dy][4]=b4.x; vin[dy][5]=b4.y; vin[dy][6]=b4.z; vin[dy][7]=b4.w;
                vin[dy][8]=sIn[icL][base + 8];
                vin[dy][9]=sIn[icL][base + 9];
            }

            #pragma unroll
            for (int j = 0; j < OCPT; j++) {
                const float4* w4 = (const float4*)&sW[icL][(ocg*OCPT + j)*12];
                float4 wA = w4[0], wB = w4[1];
                float  w8 = sW[icL][(ocg*OCPT + j)*12 + 8];
                #pragma unroll
                for (int p = 0; p < 8; p++) {
                    float s = acc[j][p];
                    s += wA.x*vin[0][p]; s += wA.y*vin[0][p+1]; s += wA.z*vin[0][p+2];
                    s += wA.w*vin[1][p]; s += wB.x*vin[1][p+1]; s += wB.y*vin[1][p+2];
                    s += wB.z*vin[2][p]; s += wB.w*vin[2][p+1]; s += w8  *vin[2][p+2];
                    acc[j][p] = s;
                }
            }
        }
    }

    const int y = y0 + r;
    #pragma unroll
    for (int j = 0; j < OCPT; j++) {
        int oc = ocg*OCPT + j;
        if (MODE == 1 && oc >= 27) continue;
        #pragma unroll
        for (int p = 0; p < 8; p++) {
            int x = x0 + xb + p;
            float v = acc[j][p];
            if (MODE == 0) {
                g_feat[(((b*Hh + y)*Ww + x) << 6) + oc] = v;
            } else {
                if (oc >= 18) v = 2.f / (1.f + expf(-v));
                g_offmod[(((b*Hh + y)*Ww + x) << 5) + oc] = v;
            }
        }
    }
}

// ---------------- deformable sampling + DCN GEMM (smem-staged) ----------------
// Block: 16x16 px tile, 64 oc, 256 threads.
// sF: staged feat window 22x22 (halo ±3), ch stride 68.  sA: sampled [256 px][72].
// sW: [c][oc] tap slice. Thread = 8 px (stride 32) x 8 oc.
#define FW 22
#define FST 68
#define AST 72

__global__ __launch_bounds__(256, 1)
void dcn_kernel(const float* __restrict__ bdcn, float* __restrict__ out)
{
    extern __shared__ float sm[];
    float* sF = sm;                         // 22*22*68 = 32912 floats
    float* sA = sm + FW*FW*FST;             // 256*72   = 18432
    float* sW = sA + 256*AST;               // 64*64    = 4096

    const int tid = threadIdx.x;
    const int b   = blockIdx.z;
    const int y0  = blockIdx.y << 4;
    const int x0  = blockIdx.x << 4;

    // ---- stage feat window (zero-filled outside image) ----
    for (int i = tid; i < FW*FW*16; i += 256) {
        int px = i >> 4, cs = (i & 15) << 2;
        int row = px / FW, col = px - row*FW;
        int gy = y0 - 3 + row, gx = x0 - 3 + col;
        float4 v = make_float4(0.f, 0.f, 0.f, 0.f);
        if ((unsigned)gy < (unsigned)Hh && (unsigned)gx < (unsigned)Ww)
            v = *(const float4*)&g_feat[(((b*Hh + gy)*Ww + gx) << 6) + cs];
        *(float4*)&sF[px*FST + cs] = v;
    }

    // sampling role: thread = pixel tid
    const int ar = tid >> 4, ac = tid & 15;
    const int ay = y0 + ar, ax = x0 + ac;
    const float* __restrict__ omp = &g_offmod[(((b*Hh + ay)*Ww + ax)) << 5];

    // GEMM role
    const int pxg = tid >> 3;       // 0..31
    const int ocg = tid & 7;        // 0..7

    float acc[8][8];
    #pragma unroll
    for (int i = 0; i < 8; i++)
        #pragma unroll
        for (int j = 0; j < 8; j++) acc[i][j] = 0.f;

    __syncthreads();

    for (int k = 0; k < 9; k++) {
        // load wdcn tap slice [c][oc] (coalesced)
        #pragma unroll 4
        for (int i = tid; i < 4096; i += 256) sW[i] = g_wdcnt[(k << 12) + i];

        // ---- bilinear sample into sA ----
        {
            float dy = omp[2*k], dxo = omp[2*k + 1], m = omp[18 + k];
            int ki = k/3 - 1, kj = k - (k/3)*3 - 1;
            float py  = (float)(ay + ki) + dy;
            float pxf = (float)(ax + kj) + dxo;
            float fy = floorf(py), fx = floorf(pxf);
            float wy = py - fy, wx = pxf - fx;
            int iy0 = (int)fy, ix0 = (int)fx;
            float w00 = m*(1.f-wy)*(1.f-wx), w01 = m*(1.f-wy)*wx;
            float w10 = m*wy*(1.f-wx),       w11 = m*wy*wx;
            float* dst = &sA[tid*AST];
            int ry = iy0 - y0 + 3, rx = ix0 - x0 + 3;
            if ((unsigned)ry <= (unsigned)(FW-2) && (unsigned)rx <= (unsigned)(FW-2)) {
                // fast path: all 4 corners staged (zeros already model padding)
                const float* base = &sF[(ry*FW + rx)*FST];
                const float4* q00 = (const float4*)base;
                const float4* q01 = (const float4*)(base + FST);
                const float4* q10 = (const float4*)(base + FW*FST);
                const float4* q11 = (const float4*)(base + FW*FST + FST);
                #pragma unroll
                for (int j = 0; j < 16; j++) {
                    float4 c00 = q00[j], c01 = q01[j], c10 = q10[j], c11 = q11[j];
                    float4 rv;
                    rv.x = w00*c00.x + w01*c01.x + w10*c10.x + w11*c11.x;
                    rv.y = w00*c00.y + w01*c01.y + w10*c10.y + w11*c11.y;
                    rv.z = w00*c00.z + w01*c01.z + w10*c10.z + w11*c11.z;
                    rv.w = w00*c00.w + w01*c01.w + w10*c10.w + w11*c11.w;
                    *(float4*)&dst[4*j] = rv;
                }
            } else {
                // slow path: global gather with validity masks
                int iy1 = iy0 + 1, ix1 = ix0 + 1;
                bool vy0 = (iy0 >= 0) && (iy0 < Hh);
                bool vy1 = (iy1 >= 0) && (iy1 < Hh);
                bool vx0 = (ix0 >= 0) && (ix0 < Ww);
                bool vx1 = (ix1 >= 0) && (ix1 < Ww);
                float m00 = w00 * ((vy0 && vx0) ? 1.f : 0.f);
                float m01 = w01 * ((vy0 && vx1) ? 1.f : 0.f);
                float m10 = w10 * ((vy1 && vx0) ? 1.f : 0.f);
                float m11 = w11 * ((vy1 && vx1) ? 1.f : 0.f);
                int cy0 = min(max(iy0, 0), Hh-1), cx0 = min(max(ix0, 0), Ww-1);
                int cy1 = min(max(iy1, 0), Hh-1), cx1 = min(max(ix1, 0), Ww-1);
                const float4* p00 = (const float4*)&g_feat[(((b*Hh + cy0)*Ww + cx0) << 6)];
                const float4* p01 = (const float4*)&g_feat[(((b*Hh + cy0)*Ww + cx1) << 6)];
                const float4* p10 = (const float4*)&g_feat[(((b*Hh + cy1)*Ww + cx0) << 6)];
                const float4* p11 = (const float4*)&g_feat[(((b*Hh + cy1)*Ww + cx1) << 6)];
                #pragma unroll
                for (int j = 0; j < 16; j++) {
                    float4 c00 = p00[j], c01 = p01[j], c10 = p10[j], c11 = p11[j];
                    float4 rv;
                    rv.x = m00*c00.x + m01*c01.x + m10*c10.x + m11*c11.x;
                    rv.y = m00*c00.y + m01*c01.y + m10*c10.y + m11*c11.y;
                    rv.z = m00*c00.z + m01*c01.z + m10*c10.z + m11*c11.z;
                    rv.w = m00*c00.w + m01*c01.w + m10*c10.w + m11*c11.w;
                    *(float4*)&dst[4*j] = rv;
                }
            }
        }
        __syncthreads();

        // ---- GEMM: acc[8px][8oc] += sA * sW over 64 channels ----
        #pragma unroll 2
        for (int c0 = 0; c0 < 64; c0 += 4) {
            float4 av[8];
            #pragma unroll
            for (int i = 0; i < 8; i++)
                av[i] = *(const float4*)&sA[(pxg + 32*i)*AST + c0];
            #pragma unroll
            for (int cc = 0; cc < 4; cc++) {
                float4 wl = *(const float4*)&sW[(c0 + cc)*64 + ocg*8];
                float4 wh = *(const float4*)&sW[(c0 + cc)*64 + ocg*8 + 4];
                #pragma unroll
                for (int i = 0; i < 8; i++) {
                    float a = (cc == 0) ? av[i].x : (cc == 1) ? av[i].y
                            : (cc == 2) ? av[i].z : av[i].w;
                    acc[i][0] += a*wl.x; acc[i][1] += a*wl.y;
                    acc[i][2] += a*wl.z; acc[i][3] += a*wl.w;
                    acc[i][4] += a*wh.x; acc[i][5] += a*wh.y;
                    acc[i][6] += a*wh.z; acc[i][7] += a*wh.w;
                }
            }
        }
        __syncthreads();
    }

    // ---- epilogue: NCHW output ----
    #pragma unroll
    for (int j = 0; j < 8; j++) {
        int oc = ocg*8 + j;
        float bv = bdcn[oc];
        #pragma unroll
        for (int i = 0; i < 8; i++) {
            int p = pxg + 32*i;
            int row = p >> 4, col = p & 15;
            out[((b*64 + oc)*Hh + y0 + row)*Ww + x0 + col] = acc[i][j] + bv;
        }
    }
}

// ---------------- launch ----------------
extern "C" void kernel_launch(void* const* d_in, const int* in_sizes, int n_in,
                              void* d_out, int out_size)
{
    const float* x_vq  = (const float*)d_in[0];
    const float* x_res = (const float*)d_in[1];
    const float* W1    = (const float*)d_in[2];
    const float* b1    = (const float*)d_in[3];
    const float* Woff  = (const float*)d_in[4];
    const float* boff  = (const float*)d_in[5];
    const float* Wmod  = (const float*)d_in[6];
    const float* bmod  = (const float*)d_in[7];
    const float* Wdcn  = (const float*)d_in[8];
    const float* bdcn  = (const float*)d_in[9];
    float* out = (float*)d_out;

    prep_kernel<<<(128*64*12 + 255)/256, 256>>>(W1, Woff, Wmod, Wdcn, boff, bmod);

    {
        dim3 grid(Ww/32, Hh/8, Bn);
        conv3x3_kernel<128, 64, 8, 0><<<grid, 256>>>(x_vq, x_res, b1);
    }
    {
        dim3 grid(Ww/32, Hh/8, Bn);
        conv3x3_kernel<64, 32, 4, 1><<<grid, 256>>>(nullptr, nullptr, nullptr);
    }
    {
        const int smem_bytes = (FW*FW*FST + 256*AST + 64*64) * (int)sizeof(float);
        cudaFuncSetAttribute(dcn_kernel, cudaFuncAttributeMaxDynamicSharedMemorySize, smem_bytes);
        dim3 grid(Ww/16, Hh/16, Bn);
        dcn_kernel<<<grid, 256, smem_bytes>>>(bdcn, out);
    }
}

// round 6
// speedup vs baseline: 1.3171x; 1.0667x over previous
#include <cuda_runtime.h>
#include <math.h>

#define Bn 8
#define Hh 128
#define Ww 128

// ---------------- device scratch ----------------
__device__ float g_feat[Bn*Hh*Ww*64];      // NHWC feat
__device__ float g_offmod[Bn*Hh*Ww*32];    // NHWC off(18)+mod(9)
__device__ float g_w1t[128*64*12];         // [ic][oc][tap12]
__device__ float g_w2t[64*32*12];          // [ic][oc32][tap12]
__device__ float g_wdcnt[9*64*64];         // [tap][c][oc]
__device__ float g_b2[32];

// ---------------- weight transpose / merge ----------------
__global__ void prep_kernel(const float* __restrict__ W1,
                            const float* __restrict__ Woff,
                            const float* __restrict__ Wmod,
                            const float* __restrict__ Wdcn,
                            const float* __restrict__ boff,
                            const float* __restrict__ bmod)
{
    int i = blockIdx.x * blockDim.x + threadIdx.x;
    if (i < 128*64*12) {                 // W1 [oc][ic][9] -> [ic][oc][12]
        int ic = i / 768; int rem = i - ic*768;
        int oc = rem / 12; int t = rem - oc*12;
        g_w1t[i] = (t < 9) ? W1[(oc*128 + ic)*9 + t] : 0.f;
    }
    if (i < 64*32*12) {                  // Woff(18)+Wmod(9)+pad -> [ic][oc32][12]
        int ic = i / 384; int rem = i - ic*384;
        int oc = rem / 12; int t = rem - oc*12;
        float v = 0.f;
        if (t < 9) {
            if (oc < 18)      v = Woff[(oc*64 + ic)*9 + t];
            else if (oc < 27) v = Wmod[((oc-18)*64 + ic)*9 + t];
        }
        g_w2t[i] = v;
    }
    if (i < 9*64*64) {                   // Wdcn [oc][c][9] -> [tap][c][oc]
        int k = i >> 12;
        int c = (i >> 6) & 63;
        int oc = i & 63;
        g_wdcnt[i] = Wdcn[(oc*64 + c)*9 + k];
    }
    if (i < 32) g_b2[i] = (i < 18) ? boff[i] : (i < 27 ? bmod[i-18] : 0.f);
}

// ---------------- generic fused 3x3 conv ----------------
// Tile: 8 rows x 32 cols, all OC. 256 threads; thread = OCPT oc x 8 px.
template<int IC, int OC, int OCPT, int MODE>
__global__ __launch_bounds__(256)
void conv3x3_kernel(const float* __restrict__ in0,
                    const float* __restrict__ in1,
                    const float* __restrict__ bias1)
{
    constexpr int OCG = OC / OCPT;
    constexpr int NT  = OCG * 32;      // 256
    constexpr int ICB = 8;
    constexpr int RS  = 36;            // padded smem row stride

    __shared__ float sIn[ICB][10*RS];
    __shared__ float sW[ICB][OC*12];

    const float* __restrict__ wT   = (MODE == 0) ? g_w1t : g_w2t;
    const float* __restrict__ bias = (MODE == 0) ? bias1 : g_b2;

    const int tid  = threadIdx.x;
    const int b    = blockIdx.z;
    const int y0   = blockIdx.y << 3;
    const int x0   = blockIdx.x << 5;
    const int ocg  = tid >> 5;
    const int lane = tid & 31;
    const int r    = lane >> 2;
    const int xb   = (lane & 3) << 3;

    float acc[OCPT][8];
    #pragma unroll
    for (int j = 0; j < OCPT; j++) {
        float bv = bias[ocg*OCPT + j];
        #pragma unroll
        for (int p = 0; p < 8; p++) acc[j][p] = bv;
    }

    for (int ic0 = 0; ic0 < IC; ic0 += ICB) {
        __syncthreads();
        for (int i = tid; i < ICB*340; i += NT) {
            int icL = i / 340; int rem = i - icL*340;
            int rr = rem / 34; int cc = rem - rr*34;
            int gy = y0 - 1 + rr, gx = x0 - 1 + cc;
            float v = 0.f;
            if ((unsigned)gy < (unsigned)Hh && (unsigned)gx < (unsigned)Ww) {
                int ic = ic0 + icL;
                if (MODE == 0) {
                    const float* src = (ic < 64) ? in0 : in1;
                    v = src[((b*64 + (ic & 63))*Hh + gy)*Ww + gx];
                } else {
                    v = g_feat[(((b*Hh + gy)*Ww + gx) << 6) + ic];
                }
            }
            sIn[icL][rr*RS + cc] = v;
        }
        for (int i = tid; i < ICB*OC*12; i += NT) {
            int icL = i / (OC*12); int j = i - icL*(OC*12);
            sW[icL][j] = wT[(ic0 + icL)*(OC*12) + j];
        }
        __syncthreads();

        #pragma unroll
        for (int icL = 0; icL < ICB; icL++) {
            float vin[3][10];
            #pragma unroll
            for (int dy = 0; dy < 3; dy++) {
                int base = (r + dy)*RS + xb;
                float4 a4 = *(const float4*)&sIn[icL][base];
                float4 b4 = *(const float4*)&sIn[icL][base + 4];
                vin[dy][0]=a4.x; vin[dy][1]=a4.y; vin[dy][2]=a4.z; vin[dy][3]=a4.w;
                vin[dy][4]=b4.x; vin[dy][5]=b4.y; vin[dy][6]=b4.z; vin[dy][7]=b4.w;
                vin[dy][8]=sIn[icL][base + 8];
                vin[dy][9]=sIn[icL][base + 9];
            }

            #pragma unroll
            for (int j = 0; j < OCPT; j++) {
                const float4* w4 = (const float4*)&sW[icL][(ocg*OCPT + j)*12];
                float4 wA = w4[0], wB = w4[1];
                float  w8 = sW[icL][(ocg*OCPT + j)*12 + 8];
                #pragma unroll
                for (int p = 0; p < 8; p++) {
                    float s = acc[j][p];
                    s += wA.x*vin[0][p]; s += wA.y*vin[0][p+1]; s += wA.z*vin[0][p+2];
                    s += wA.w*vin[1][p]; s += wB.x*vin[1][p+1]; s += wB.y*vin[1][p+2];
                    s += wB.z*vin[2][p]; s += wB.w*vin[2][p+1]; s += w8  *vin[2][p+2];
                    acc[j][p] = s;
                }
            }
        }
    }

    const int y = y0 + r;
    #pragma unroll
    for (int j = 0; j < OCPT; j++) {
        int oc = ocg*OCPT + j;
        if (MODE == 1 && oc >= 27) continue;
        #pragma unroll
        for (int p = 0; p < 8; p++) {
            int x = x0 + xb + p;
            float v = acc[j][p];
            if (MODE == 0) {
                g_feat[(((b*Hh + y)*Ww + x) << 6) + oc] = v;
            } else {
                if (oc >= 18) v = 2.f / (1.f + expf(-v));
                g_offmod[(((b*Hh + y)*Ww + x) << 5) + oc] = v;
            }
        }
    }
}

// ---------------- deformable sampling + DCN GEMM (smem-staged) ----------------
// Block: 16x16 px tile, 64 oc, 512 threads.
// sF: staged feat window 22x22 (halo ±3), ch stride 68 (f32).
// sA: sampled [256 px][68].  sW: [c][64 oc] tap slice.
// Sampling: 2 threads per pixel (32 ch each).
// GEMM: thread = 4 px (stride 64) x 8 oc (ocg*4 and 32+ocg*4 halves).
#define FW 22
#define FST 68
#define AST 68

__global__ __launch_bounds__(512, 1)
void dcn_kernel(const float* __restrict__ bdcn, float* __restrict__ out)
{
    extern __shared__ float sm[];
    float* sF = sm;                         // 22*22*68 = 32912 floats
    float* sA = sm + FW*FW*FST;             // 256*68   = 17408
    float* sW = sA + 256*AST;               // 64*64    = 4096

    const int tid = threadIdx.x;
    const int b   = blockIdx.z;
    const int y0  = blockIdx.y << 4;
    const int x0  = blockIdx.x << 4;

    // ---- stage feat window (zero-filled outside image) ----
    for (int i = tid; i < FW*FW*16; i += 512) {
        int px = i >> 4, cs = (i & 15) << 2;
        int row = px / FW, col = px - row*FW;
        int gy = y0 - 3 + row, gx = x0 - 3 + col;
        float4 v = make_float4(0.f, 0.f, 0.f, 0.f);
        if ((unsigned)gy < (unsigned)Hh && (unsigned)gx < (unsigned)Ww)
            v = *(const float4*)&g_feat[(((b*Hh + gy)*Ww + gx) << 6) + cs];
        *(float4*)&sF[px*FST + cs] = v;
    }

    // sampling role: 2 threads per pixel
    const int pl    = tid >> 1;           // 0..255 raster (r*16 + c)
    const int chalf = (tid & 1) << 5;     // 0 or 32
    const int ar = pl >> 4, ac = pl & 15;
    const int ay = y0 + ar, ax = x0 + ac;
    const float* __restrict__ omp = &g_offmod[(((b*Hh + ay)*Ww + ax)) << 5];

    // GEMM role: thread = 4 px x 8 oc
    const int pxq = tid >> 3;       // 0..63 -> pixels pxq + 64*i
    const int ocg = tid & 7;        // oc = ocg*4+j (j<4), 32+ocg*4+(j-4)

    float acc[4][8];
    #pragma unroll
    for (int i = 0; i < 4; i++)
        #pragma unroll
        for (int j = 0; j < 8; j++) acc[i][j] = 0.f;

    __syncthreads();

    for (int k = 0; k < 9; k++) {
        // load wdcn tap slice [c][oc] (coalesced)
        #pragma unroll 4
        for (int i = tid; i < 4096; i += 512) sW[i] = g_wdcnt[(k << 12) + i];

        // ---- bilinear sample 32 channels into sA ----
        {
            float dy = omp[2*k], dxo = omp[2*k + 1], m = omp[18 + k];
            int ki = k/3 - 1, kj = k - (k/3)*3 - 1;
            float py  = (float)(ay + ki) + dy;
            float pxf = (float)(ax + kj) + dxo;
            float fy = floorf(py), fx = floorf(pxf);
            float wy = py - fy, wx = pxf - fx;
            int iy0 = (int)fy, ix0 = (int)fx;
            float w00 = m*(1.f-wy)*(1.f-wx), w01 = m*(1.f-wy)*wx;
            float w10 = m*wy*(1.f-wx),       w11 = m*wy*wx;
            float* dst = &sA[pl*AST + chalf];
            int ry = iy0 - y0 + 3, rx = ix0 - x0 + 3;
            if ((unsigned)ry <= (unsigned)(FW-2) && (unsigned)rx <= (unsigned)(FW-2)) {
                // fast path: all 4 corners staged (zeros model padding)
                const float* base = &sF[(ry*FW + rx)*FST + chalf];
                const float4* q00 = (const float4*)base;
                const float4* q01 = (const float4*)(base + FST);
                const float4* q10 = (const float4*)(base + FW*FST);
                const float4* q11 = (const float4*)(base + FW*FST + FST);
                #pragma unroll
                for (int j = 0; j < 8; j++) {
                    float4 c00 = q00[j], c01 = q01[j], c10 = q10[j], c11 = q11[j];
                    float4 rv;
                    rv.x = w00*c00.x + w01*c01.x + w10*c10.x + w11*c11.x;
                    rv.y = w00*c00.y + w01*c01.y + w10*c10.y + w11*c11.y;
                    rv.z = w00*c00.z + w01*c01.z + w10*c10.z + w11*c11.z;
                    rv.w = w00*c00.w + w01*c01.w + w10*c10.w + w11*c11.w;
                    *(float4*)&dst[4*j] = rv;
                }
            } else {
                // slow path: global gather with validity masks
                int iy1 = iy0 + 1, ix1 = ix0 + 1;
                bool vy0 = (iy0 >= 0) && (iy0 < Hh);
                bool vy1 = (iy1 >= 0) && (iy1 < Hh);
                bool vx0 = (ix0 >= 0) && (ix0 < Ww);
                bool vx1 = (ix1 >= 0) && (ix1 < Ww);
                float m00 = w00 * ((vy0 && vx0) ? 1.f : 0.f);
                float m01 = w01 * ((vy0 && vx1) ? 1.f : 0.f);
                float m10 = w10 * ((vy1 && vx0) ? 1.f : 0.f);
                float m11 = w11 * ((vy1 && vx1) ? 1.f : 0.f);
                int cy0 = min(max(iy0, 0), Hh-1), cx0 = min(max(ix0, 0), Ww-1);
                int cy1 = min(max(iy1, 0), Hh-1), cx1 = min(max(ix1, 0), Ww-1);
                const float4* p00 = (const float4*)&g_feat[(((b*Hh + cy0)*Ww + cx0) << 6) + chalf];
                const float4* p01 = (const float4*)&g_feat[(((b*Hh + cy0)*Ww + cx1) << 6) + chalf];
                const float4* p10 = (const float4*)&g_feat[(((b*Hh + cy1)*Ww + cx0) << 6) + chalf];
                const float4* p11 = (const float4*)&g_feat[(((b*Hh + cy1)*Ww + cx1) << 6) + chalf];
                #pragma unroll
                for (int j = 0; j < 8; j++) {
                    float4 c00 = p00[j], c01 = p01[j], c10 = p10[j], c11 = p11[j];
                    float4 rv;
                    rv.x = m00*c00.x + m01*c01.x + m10*c10.x + m11*c11.x;
                    rv.y = m00*c00.y + m01*c01.y + m10*c10.y + m11*c11.y;
                    rv.z = m00*c00.z + m01*c01.z + m10*c10.z + m11*c11.z;
                    rv.w = m00*c00.w + m01*c01.w + m10*c10.w + m11*c11.w;
                    *(float4*)&dst[4*j] = rv;
                }
            }
        }
        __syncthreads();

        // ---- GEMM: acc[4px][8oc] += sA * sW over 64 channels ----
        #pragma unroll 2
        for (int c0 = 0; c0 < 64; c0 += 4) {
            float4 av[4];
            #pragma unroll
            for (int i = 0; i < 4; i++)
                av[i] = *(const float4*)&sA[(pxq + 64*i)*AST + c0];
            #pragma unroll
            for (int cc = 0; cc < 4; cc++) {
                float4 wl = *(const float4*)&sW[(c0 + cc)*64 + ocg*4];
                float4 wh = *(const float4*)&sW[(c0 + cc)*64 + 32 + ocg*4];
                #pragma unroll
                for (int i = 0; i < 4; i++) {
                    float a = (cc == 0) ? av[i].x : (cc == 1) ? av[i].y
                            : (cc == 2) ? av[i].z : av[i].w;
                    acc[i][0] += a*wl.x; acc[i][1] += a*wl.y;
                    acc[i][2] += a*wl.z; acc[i][3] += a*wl.w;
                    acc[i][4] += a*wh.x; acc[i][5] += a*wh.y;
                    acc[i][6] += a*wh.z; acc[i][7] += a*wh.w;
                }
            }
        }
        __syncthreads();
    }

    // ---- epilogue: NCHW output ----
    #pragma unroll
    for (int j = 0; j < 8; j++) {
        int oc = (j < 4) ? (ocg*4 + j) : (32 + ocg*4 + (j - 4));
        float bv = bdcn[oc];
        #pragma unroll
        for (int i = 0; i < 4; i++) {
            int p = pxq + 64*i;
            int row = p >> 4, col = p & 15;
            out[((b*64 + oc)*Hh + y0 + row)*Ww + x0 + col] = acc[i][j] + bv;
        }
    }
}

// ---------------- launch ----------------
extern "C" void kernel_launch(void* const* d_in, const int* in_sizes, int n_in,
                              void* d_out, int out_size)
{
    const float* x_vq  = (const float*)d_in[0];
    const float* x_res = (const float*)d_in[1];
    const float* W1    = (const float*)d_in[2];
    const float* b1    = (const float*)d_in[3];
    const float* Woff  = (const float*)d_in[4];
    const float* boff  = (const float*)d_in[5];
    const float* Wmod  = (const float*)d_in[6];
    const float* bmod  = (const float*)d_in[7];
    const float* Wdcn  = (const float*)d_in[8];
    const float* bdcn  = (const float*)d_in[9];
    float* out = (float*)d_out;

    prep_kernel<<<(128*64*12 + 255)/256, 256>>>(W1, Woff, Wmod, Wdcn, boff, bmod);

    {
        dim3 grid(Ww/32, Hh/8, Bn);
        conv3x3_kernel<128, 64, 8, 0><<<grid, 256>>>(x_vq, x_res, b1);
    }
    {
        dim3 grid(Ww/32, Hh/8, Bn);
        conv3x3_kernel<64, 32, 4, 1><<<grid, 256>>>(nullptr, nullptr, nullptr);
    }
    {
        const int smem_bytes = (FW*FW*FST + 256*AST + 64*64) * (int)sizeof(float);
        cudaFuncSetAttribute(dcn_kernel, cudaFuncAttributeMaxDynamicSharedMemorySize, smem_bytes);
        dim3 grid(Ww/16, Hh/16, Bn);
        dcn_kernel<<<grid, 512, smem_bytes>>>(bdcn, out);
    }
}

// round 9
// speedup vs baseline: 1.3199x; 1.0021x over previous
#include <cuda_runtime.h>
#include <math.h>

#define Bn 8
#define Hh 128
#define Ww 128

// ---------------- device scratch ----------------
__device__ float g_feat[Bn*Hh*Ww*64];      // NHWC feat
__device__ float g_offmod[Bn*Hh*Ww*32];    // NHWC off(18)+mod(9)
__device__ float g_w1t[128*64*12];         // [ic][oc][tap12]
__device__ float g_w2t[64*32*12];          // [ic][oc32][tap12]
__device__ float g_wdcnt[9*64*64];         // [tap][c][oc]
__device__ float g_b2[32];

// ---------------- weight transpose / merge ----------------
__global__ void prep_kernel(const float* __restrict__ W1,
                            const float* __restrict__ Woff,
                            const float* __restrict__ Wmod,
                            const float* __restrict__ Wdcn,
                            const float* __restrict__ boff,
                            const float* __restrict__ bmod)
{
    int i = blockIdx.x * blockDim.x + threadIdx.x;
    if (i < 128*64*12) {                 // W1 [oc][ic][9] -> [ic][oc][12]
        int ic = i / 768; int rem = i - ic*768;
        int oc = rem / 12; int t = rem - oc*12;
        g_w1t[i] = (t < 9) ? W1[(oc*128 + ic)*9 + t] : 0.f;
    }
    if (i < 64*32*12) {                  // Woff(18)+Wmod(9)+pad -> [ic][oc32][12]
        int ic = i / 384; int rem = i - ic*384;
        int oc = rem / 12; int t = rem - oc*12;
        float v = 0.f;
        if (t < 9) {
            if (oc < 18)      v = Woff[(oc*64 + ic)*9 + t];
            else if (oc < 27) v = Wmod[((oc-18)*64 + ic)*9 + t];
        }
        g_w2t[i] = v;
    }
    if (i < 9*64*64) {                   // Wdcn [oc][c][9] -> [tap][c][oc]
        int k = i >> 12;
        int c = (i >> 6) & 63;
        int oc = i & 63;
        g_wdcnt[i] = Wdcn[(oc*64 + c)*9 + k];
    }
    if (i < 32) g_b2[i] = (i < 18) ? boff[i] : (i < 27 ? bmod[i-18] : 0.f);
}

// ---------------- generic fused 3x3 conv ----------------
// Tile: 8 rows x 32 cols, all OC. 256 threads; thread = OCPT oc x 8 px.
template<int IC, int OC, int OCPT, int MODE>
__global__ __launch_bounds__(256)
void conv3x3_kernel(const float* __restrict__ in0,
                    const float* __restrict__ in1,
                    const float* __restrict__ bias1)
{
    constexpr int OCG = OC / OCPT;
    constexpr int NT  = OCG * 32;      // 256
    constexpr int ICB = 8;
    constexpr int RS  = 36;            // padded smem row stride

    __shared__ float sIn[ICB][10*RS];
    __shared__ float sW[ICB][OC*12];

    const float* __restrict__ wT   = (MODE == 0) ? g_w1t : g_w2t;
    const float* __restrict__ bias = (MODE == 0) ? bias1 : g_b2;

    const int tid  = threadIdx.x;
    const int b    = blockIdx.z;
    const int y0   = blockIdx.y << 3;
    const int x0   = blockIdx.x << 5;
    const int ocg  = tid >> 5;
    const int lane = tid & 31;
    const int r    = lane >> 2;
    const int xb   = (lane & 3) << 3;

    float acc[OCPT][8];
    #pragma unroll
    for (int j = 0; j < OCPT; j++) {
        float bv = bias[ocg*OCPT + j];
        #pragma unroll
        for (int p = 0; p < 8; p++) acc[j][p] = bv;
    }

    for (int ic0 = 0; ic0 < IC; ic0 += ICB) {
        __syncthreads();
        for (int i = tid; i < ICB*340; i += NT) {
            int icL = i / 340; int rem = i - icL*340;
            int rr = rem / 34; int cc = rem - rr*34;
            int gy = y0 - 1 + rr, gx = x0 - 1 + cc;
            float v = 0.f;
            if ((unsigned)gy < (unsigned)Hh && (unsigned)gx < (unsigned)Ww) {
                int ic = ic0 + icL;
                if (MODE == 0) {
                    const float* src = (ic < 64) ? in0 : in1;
                    v = src[((b*64 + (ic & 63))*Hh + gy)*Ww + gx];
                } else {
                    v = g_feat[(((b*Hh + gy)*Ww + gx) << 6) + ic];
                }
            }
            sIn[icL][rr*RS + cc] = v;
        }
        for (int i = tid; i < ICB*OC*12; i += NT) {
            int icL = i / (OC*12); int j = i - icL*(OC*12);
            sW[icL][j] = wT[(ic0 + icL)*(OC*12) + j];
        }
        __syncthreads();

        #pragma unroll
        for (int icL = 0; icL < ICB; icL++) {
            float vin[3][10];
            #pragma unroll
            for (int dy = 0; dy < 3; dy++) {
                int base = (r + dy)*RS + xb;
                float4 a4 = *(const float4*)&sIn[icL][base];
                float4 b4 = *(const float4*)&sIn[icL][base + 4];
                vin[dy][0]=a4.x; vin[dy][1]=a4.y; vin[dy][2]=a4.z; vin[dy][3]=a4.w;
                vin[dy][4]=b4.x; vin[dy][5]=b4.y; vin[dy][6]=b4.z; vin[dy][7]=b4.w;
                vin[dy][8]=sIn[icL][base + 8];
                vin[dy][9]=sIn[icL][base + 9];
            }

            #pragma unroll
            for (int j = 0; j < OCPT; j++) {
                const float4* w4 = (const float4*)&sW[icL][(ocg*OCPT + j)*12];
                float4 wA = w4[0], wB = w4[1];
                float  w8 = sW[icL][(ocg*OCPT + j)*12 + 8];
                #pragma unroll
                for (int p = 0; p < 8; p++) {
                    float s = acc[j][p];
                    s += wA.x*vin[0][p]; s += wA.y*vin[0][p+1]; s += wA.z*vin[0][p+2];
                    s += wA.w*vin[1][p]; s += wB.x*vin[1][p+1]; s += wB.y*vin[1][p+2];
                    s += wB.z*vin[2][p]; s += wB.w*vin[2][p+1]; s += w8  *vin[2][p+2];
                    acc[j][p] = s;
                }
            }
        }
    }

    const int y = y0 + r;
    #pragma unroll
    for (int j = 0; j < OCPT; j++) {
        int oc = ocg*OCPT + j;
        if (MODE == 1 && oc >= 27) continue;
        #pragma unroll
        for (int p = 0; p < 8; p++) {
            int x = x0 + xb + p;
            float v = acc[j][p];
            if (MODE == 0) {
                g_feat[(((b*Hh + y)*Ww + x) << 6) + oc] = v;
            } else {
                if (oc >= 18) v = 2.f / (1.f + expf(-v));
                g_offmod[(((b*Hh + y)*Ww + x) << 5) + oc] = v;
            }
        }
    }
}

// ---------------- deformable sampling + DCN GEMM (smem-staged) ----------------
// Block: 16x16 px tile, 64 oc, 512 threads.
// sF: staged feat window 22x22 (halo ±3), ch stride 68 (f32).
// sA: sampled [256 px][68].  sW: [c][64 oc] tap slice.
// Sampling: 2 threads per pixel (32 ch each).
// GEMM: pxq = tid&63, ocg = tid>>6 -> warp-uniform oc group => weight LDS
// broadcasts (single-address per phase), A-loads conflict-free (17 mod 8 = 1).
#define FW 22
#define FST 68
#define AST 68

__global__ __launch_bounds__(512, 1)
void dcn_kernel(const float* __restrict__ bdcn, float* __restrict__ out)
{
    extern __shared__ float sm[];
    float* sF = sm;                         // 22*22*68 = 32912 floats
    float* sA = sm + FW*FW*FST;             // 256*68   = 17408
    float* sW = sA + 256*AST;               // 64*64    = 4096

    const int tid = threadIdx.x;
    const int b   = blockIdx.z;
    const int y0  = blockIdx.y << 4;
    const int x0  = blockIdx.x << 4;

    // ---- stage feat window (zero-filled outside image) ----
    for (int i = tid; i < FW*FW*16; i += 512) {
        int px = i >> 4, cs = (i & 15) << 2;
        int row = px / FW, col = px - row*FW;
        int gy = y0 - 3 + row, gx = x0 - 3 + col;
        float4 v = make_float4(0.f, 0.f, 0.f, 0.f);
        if ((unsigned)gy < (unsigned)Hh && (unsigned)gx < (unsigned)Ww)
            v = *(const float4*)&g_feat[(((b*Hh + gy)*Ww + gx) << 6) + cs];
        *(float4*)&sF[px*FST + cs] = v;
    }

    // sampling role: 2 threads per pixel
    const int pl    = tid >> 1;           // 0..255 raster (r*16 + c)
    const int chalf = (tid & 1) << 5;     // 0 or 32
    const int ar = pl >> 4, ac = pl & 15;
    const int ay = y0 + ar, ax = x0 + ac;
    const float* __restrict__ omp = &g_offmod[(((b*Hh + ay)*Ww + ax)) << 5];

    // GEMM role: thread = 4 px (stride 64) x 8 contiguous oc.
    // All lanes of a warp share ocg -> weight loads are warp-broadcast.
    const int pxq = tid & 63;       // pixels pxq + 64*i
    const int ocg = tid >> 6;       // 0..7 ; oc = ocg*8 + j

    float acc[4][8];
    #pragma unroll
    for (int i = 0; i < 4; i++)
        #pragma unroll
        for (int j = 0; j < 8; j++) acc[i][j] = 0.f;

    __syncthreads();

    for (int k = 0; k < 9; k++) {
        // load wdcn tap slice [c][oc] (coalesced)
        #pragma unroll 4
        for (int i = tid; i < 4096; i += 512) sW[i] = g_wdcnt[(k << 12) + i];

        // ---- bilinear sample 32 channels into sA ----
        {
            float dy = omp[2*k], dxo = omp[2*k + 1], m = omp[18 + k];
            int ki = k/3 - 1, kj = k - (k/3)*3 - 1;
            float py  = (float)(ay + ki) + dy;
            float pxf = (float)(ax + kj) + dxo;
            float fy = floorf(py), fx = floorf(pxf);
            float wy = py - fy, wx = pxf - fx;
            int iy0 = (int)fy, ix0 = (int)fx;
            float w00 = m*(1.f-wy)*(1.f-wx), w01 = m*(1.f-wy)*wx;
            float w10 = m*wy*(1.f-wx),       w11 = m*wy*wx;
            float* dst = &sA[pl*AST + chalf];
            int ry = iy0 - y0 + 3, rx = ix0 - x0 + 3;
            if ((unsigned)ry <= (unsigned)(FW-2) && (unsigned)rx <= (unsigned)(FW-2)) {
                // fast path: all 4 corners staged (zeros model padding)
                const float* base = &sF[(ry*FW + rx)*FST + chalf];
                const float4* q00 = (const float4*)base;
                const float4* q01 = (const float4*)(base + FST);
                const float4* q10 = (const float4*)(base + FW*FST);
                const float4* q11 = (const float4*)(base + FW*FST + FST);
                #pragma unroll
                for (int j = 0; j < 8; j++) {
                    float4 c00 = q00[j], c01 = q01[j], c10 = q10[j], c11 = q11[j];
                    float4 rv;
                    rv.x = w00*c00.x + w01*c01.x + w10*c10.x + w11*c11.x;
                    rv.y = w00*c00.y + w01*c01.y + w10*c10.y + w11*c11.y;
                    rv.z = w00*c00.z + w01*c01.z + w10*c10.z + w11*c11.z;
                    rv.w = w00*c00.w + w01*c01.w + w10*c10.w + w11*c11.w;
                    *(float4*)&dst[4*j] = rv;
                }
            } else {
                // slow path: global gather with validity masks
                int iy1 = iy0 + 1, ix1 = ix0 + 1;
                bool vy0 = (iy0 >= 0) && (iy0 < Hh);
                bool vy1 = (iy1 >= 0) && (iy1 < Hh);
                bool vx0 = (ix0 >= 0) && (ix0 < Ww);
                bool vx1 = (ix1 >= 0) && (ix1 < Ww);
                float m00 = w00 * ((vy0 && vx0) ? 1.f : 0.f);
                float m01 = w01 * ((vy0 && vx1) ? 1.f : 0.f);
                float m10 = w10 * ((vy1 && vx0) ? 1.f : 0.f);
                float m11 = w11 * ((vy1 && vx1) ? 1.f : 0.f);
                int cy0 = min(max(iy0, 0), Hh-1), cx0 = min(max(ix0, 0), Ww-1);
                int cy1 = min(max(iy1, 0), Hh-1), cx1 = min(max(ix1, 0), Ww-1);
                const float4* p00 = (const float4*)&g_feat[(((b*Hh + cy0)*Ww + cx0) << 6) + chalf];
                const float4* p01 = (const float4*)&g_feat[(((b*Hh + cy0)*Ww + cx1) << 6) + chalf];
                const float4* p10 = (const float4*)&g_feat[(((b*Hh + cy1)*Ww + cx0) << 6) + chalf];
                const float4* p11 = (const float4*)&g_feat[(((b*Hh + cy1)*Ww + cx1) << 6) + chalf];
                #pragma unroll
                for (int j = 0; j < 8; j++) {
                    float4 c00 = p00[j], c01 = p01[j], c10 = p10[j], c11 = p11[j];
                    float4 rv;
                    rv.x = m00*c00.x + m01*c01.x + m10*c10.x + m11*c11.x;
                    rv.y = m00*c00.y + m01*c01.y + m10*c10.y + m11*c11.y;
                    rv.z = m00*c00.z + m01*c01.z + m10*c10.z + m11*c11.z;
                    rv.w = m00*c00.w + m01*c01.w + m10*c10.w + m11*c11.w;
                    *(float4*)&dst[4*j] = rv;
                }
            }
        }
        __syncthreads();

        // ---- GEMM: acc[4px][8oc] += sA * sW over 64 channels ----
        #pragma unroll 2
        for (int c0 = 0; c0 < 64; c0 += 4) {
            float4 av[4];
            #pragma unroll
            for (int i = 0; i < 4; i++)
                av[i] = *(const float4*)&sA[(pxq + 64*i)*AST + c0];
            #pragma unroll
            for (int cc = 0; cc < 4; cc++) {
                float4 wl = *(const float4*)&sW[(c0 + cc)*64 + ocg*8];      // broadcast
                float4 wh = *(const float4*)&sW[(c0 + cc)*64 + ocg*8 + 4];  // broadcast
                #pragma unroll
                for (int i = 0; i < 4; i++) {
                    float a = (cc == 0) ? av[i].x : (cc == 1) ? av[i].y
                            : (cc == 2) ? av[i].z : av[i].w;
                    acc[i][0] += a*wl.x; acc[i][1] += a*wl.y;
                    acc[i][2] += a*wl.z; acc[i][3] += a*wl.w;
                    acc[i][4] += a*wh.x; acc[i][5] += a*wh.y;
                    acc[i][6] += a*wh.z; acc[i][7] += a*wh.w;
                }
            }
        }
        __syncthreads();
    }

    // ---- epilogue: NCHW output ----
    #pragma unroll
    for (int j = 0; j < 8; j++) {
        int oc = ocg*8 + j;
        float bv = bdcn[oc];
        #pragma unroll
        for (int i = 0; i < 4; i++) {
            int p = pxq + 64*i;
            int row = p >> 4, col = p & 15;
            out[((b*64 + oc)*Hh + y0 + row)*Ww + x0 + col] = acc[i][j] + bv;
        }
    }
}

// ---------------- launch ----------------
extern "C" void kernel_launch(void* const* d_in, const int* in_sizes, int n_in,
                              void* d_out, int out_size)
{
    const float* x_vq  = (const float*)d_in[0];
    const float* x_res = (const float*)d_in[1];
    const float* W1    = (const float*)d_in[2];
    const float* b1    = (const float*)d_in[3];
    const float* Woff  = (const float*)d_in[4];
    const float* boff  = (const float*)d_in[5];
    const float* Wmod  = (const float*)d_in[6];
    const float* bmod  = (const float*)d_in[7];
    const float* Wdcn  = (const float*)d_in[8];
    const float* bdcn  = (const float*)d_in[9];
    float* out = (float*)d_out;

    prep_kernel<<<(128*64*12 + 255)/256, 256>>>(W1, Woff, Wmod, Wdcn, boff, bmod);

    {
        dim3 grid(Ww/32, Hh/8, Bn);
        conv3x3_kernel<128, 64, 8, 0><<<grid, 256>>>(x_vq, x_res, b1);
    }
    {
        dim3 grid(Ww/32, Hh/8, Bn);
        conv3x3_kernel<64, 32, 4, 1><<<grid, 256>>>(nullptr, nullptr, nullptr);
    }
    {
        const int smem_bytes = (FW*FW*FST + 256*AST + 64*64) * (int)sizeof(float);
        cudaFuncSetAttribute(dcn_kernel, cudaFuncAttributeMaxDynamicSharedMemorySize, smem_bytes);
        dim3 grid(Ww/16, Hh/16, Bn);
        dcn_kernel<<<grid, 512, smem_bytes>>>(bdcn, out);
    }
}

// round 10
// speedup vs baseline: 1.3720x; 1.0395x over previous
#include <cuda_runtime.h>
#include <math.h>

#define Bn 8
#define Hh 128
#define Ww 128

// ---------------- f32x2 packed helpers ----------------
__device__ __forceinline__ unsigned long long pack2(float lo, float hi) {
    unsigned long long r;
    asm("mov.b64 %0, {%1, %2};" : "=l"(r) : "f"(lo), "f"(hi));
    return r;
}
__device__ __forceinline__ void fma2(unsigned long long& acc,
                                     unsigned long long a, unsigned long long b) {
    asm("fma.rn.f32x2 %0, %1, %2, %0;" : "+l"(acc) : "l"(a), "l"(b));
}
__device__ __forceinline__ float2 unpack2(unsigned long long v) {
    float2 r;
    asm("mov.b64 {%0, %1}, %2;" : "=f"(r.x), "=f"(r.y) : "l"(v));
    return r;
}

// ---------------- device scratch ----------------
__device__ float g_feat[Bn*Hh*Ww*64];      // NHWC feat
__device__ float g_offmod[Bn*Hh*Ww*32];    // NHWC off(18)+mod(9)
__device__ float g_w1t[128*9*64];          // [ic][tap][oc]
__device__ float g_w2t[64*9*32];           // [ic][tap][oc32]
__device__ float g_wdcnt[9*32*64*2];       // [tap][c2][oc][parity]
__device__ float g_b2[32];

// ---------------- weight transpose / merge ----------------
__global__ void prep_kernel(const float* __restrict__ W1,
                            const float* __restrict__ Woff,
                            const float* __restrict__ Wmod,
                            const float* __restrict__ Wdcn,
                            const float* __restrict__ boff,
                            const float* __restrict__ bmod)
{
    int i = blockIdx.x * blockDim.x + threadIdx.x;
    if (i < 128*9*64) {                  // W1 [oc][ic][9] -> [ic][t][oc]
        int ic = i / 576; int rem = i - ic*576;
        int t = rem / 64; int oc = rem & 63;
        g_w1t[i] = W1[(oc*128 + ic)*9 + t];
    }
    if (i < 64*9*32) {                   // Woff(18)+Wmod(9)+pad -> [ic][t][oc32]
        int ic = i / 288; int rem = i - ic*288;
        int t = rem >> 5; int oc = rem & 31;
        float v = 0.f;
        if (oc < 18)      v = Woff[(oc*64 + ic)*9 + t];
        else if (oc < 27) v = Wmod[((oc-18)*64 + ic)*9 + t];
        g_w2t[i] = v;
    }
    if (i < 9*64*64) {                   // Wdcn [oc][c][9] -> [tap][c2][oc][par]
        int k = i >> 12;
        int r = i & 4095;
        int c2  = r >> 7;
        int oc  = (r >> 1) & 63;
        int par = i & 1;
        int c = c2*2 + par;
        g_wdcnt[i] = Wdcn[(oc*64 + c)*9 + k];
    }
    if (i < 32) g_b2[i] = (i < 18) ? boff[i] : (i < 27 ? bmod[i-18] : 0.f);
}

// ---------------- generic fused 3x3 conv (f32x2 inner) ----------------
// Tile: 8 rows x 32 cols, all OC. 256 threads; thread = OCPT oc x 8 px.
// Weights [ic][tap][oc]: adjacent oc form natural f32x2 pairs (broadcast LDS.64).
template<int IC, int OC, int OCPT, int MODE>
__global__ __launch_bounds__(256)
void conv3x3_kernel(const float* __restrict__ in0,
                    const float* __restrict__ in1,
                    const float* __restrict__ bias1)
{
    constexpr int OCG = OC / OCPT;
    constexpr int NT  = OCG * 32;      // 256
    constexpr int ICB = 8;
    constexpr int RS  = 36;            // padded smem row stride
    constexpr int JP  = OCPT / 2;      // oc pairs per thread

    __shared__ __align__(16) float sIn[ICB][10*RS];
    __shared__ __align__(16) float sW[ICB][9*OC];

    const float* __restrict__ wT   = (MODE == 0) ? g_w1t : g_w2t;
    const float* __restrict__ bias = (MODE == 0) ? bias1 : g_b2;

    const int tid  = threadIdx.x;
    const int b    = blockIdx.z;
    const int y0   = blockIdx.y << 3;
    const int x0   = blockIdx.x << 5;
    const int ocg  = tid >> 5;
    const int lane = tid & 31;
    const int r    = lane >> 2;
    const int xb   = (lane & 3) << 3;

    unsigned long long acc2[JP][8];
    #pragma unroll
    for (int j2 = 0; j2 < JP; j2++) {
        int oc0 = ocg*OCPT + 2*j2;
        unsigned long long bv = pack2(bias[oc0], bias[oc0+1]);
        #pragma unroll
        for (int p = 0; p < 8; p++) acc2[j2][p] = bv;
    }

    for (int ic0 = 0; ic0 < IC; ic0 += ICB) {
        __syncthreads();
        for (int i = tid; i < ICB*340; i += NT) {
            int icL = i / 340; int rem = i - icL*340;
            int rr = rem / 34; int cc = rem - rr*34;
            int gy = y0 - 1 + rr, gx = x0 - 1 + cc;
            float v = 0.f;
            if ((unsigned)gy < (unsigned)Hh && (unsigned)gx < (unsigned)Ww) {
                int ic = ic0 + icL;
                if (MODE == 0) {
                    const float* src = (ic < 64) ? in0 : in1;
                    v = src[((b*64 + (ic & 63))*Hh + gy)*Ww + gx];
                } else {
                    v = g_feat[(((b*Hh + gy)*Ww + gx) << 6) + ic];
                }
            }
            sIn[icL][rr*RS + cc] = v;
        }
        for (int i = tid; i < ICB*9*OC; i += NT) {
            int icL = i / (9*OC); int j = i - icL*(9*OC);
            sW[icL][j] = wT[(ic0 + icL)*(9*OC) + j];
        }
        __syncthreads();

        #pragma unroll
        for (int icL = 0; icL < ICB; icL++) {
            #pragma unroll
            for (int dy = 0; dy < 3; dy++) {
                int base = (r + dy)*RS + xb;
                float4 a4 = *(const float4*)&sIn[icL][base];
                float4 b4 = *(const float4*)&sIn[icL][base + 4];
                float v8 = sIn[icL][base + 8];
                float v9 = sIn[icL][base + 9];
                unsigned long long vb[10];
                vb[0] = pack2(a4.x, a4.x); vb[1] = pack2(a4.y, a4.y);
                vb[2] = pack2(a4.z, a4.z); vb[3] = pack2(a4.w, a4.w);
                vb[4] = pack2(b4.x, b4.x); vb[5] = pack2(b4.y, b4.y);
                vb[6] = pack2(b4.z, b4.z); vb[7] = pack2(b4.w, b4.w);
                vb[8] = pack2(v8, v8);     vb[9] = pack2(v9, v9);
                #pragma unroll
                for (int dx = 0; dx < 3; dx++) {
                    int t = dy*3 + dx;
                    unsigned long long w2[JP];
                    #pragma unroll
                    for (int j2 = 0; j2 < JP; j2++)
                        w2[j2] = *(const unsigned long long*)
                                 &sW[icL][t*OC + ocg*OCPT + 2*j2];   // broadcast
                    #pragma unroll
                    for (int p = 0; p < 8; p++) {
                        #pragma unroll
                        for (int j2 = 0; j2 < JP; j2++)
                            fma2(acc2[j2][p], vb[p+dx], w2[j2]);
                    }
                }
            }
        }
    }

    const int y = y0 + r;
    #pragma unroll
    for (int j2 = 0; j2 < JP; j2++) {
        int oc0 = ocg*OCPT + 2*j2;
        #pragma unroll
        for (int p = 0; p < 8; p++) {
            int x = x0 + xb + p;
            float2 v = unpack2(acc2[j2][p]);
            if (MODE == 0) {
                float* dst = &g_feat[(((b*Hh + y)*Ww + x) << 6)];
                dst[oc0]     = v.x;
                dst[oc0 + 1] = v.y;
            } else {
                float* dst = &g_offmod[(((b*Hh + y)*Ww + x) << 5)];
                if (oc0 < 27) {
                    float a = v.x;
                    if (oc0 >= 18) a = 2.f / (1.f + expf(-a));
                    dst[oc0] = a;
                }
                if (oc0 + 1 < 27) {
                    float a = v.y;
                    if (oc0 + 1 >= 18) a = 2.f / (1.f + expf(-a));
                    dst[oc0 + 1] = a;
                }
            }
        }
    }
}

// ---------------- deformable sampling + DCN GEMM (smem-staged, f32x2) ----------------
// Block: 16x16 px tile, 64 oc, 512 threads.
// sF: staged feat window 22x22 (halo ±3), ch stride 68.
// sA: sampled [256 px][68].  sW: [c2][oc][2] tap slice (channel-parity pairs).
// GEMM: pxq = tid&63, ocg = tid>>6 (warp-uniform -> weight broadcast).
// Accumulators are f32x2 channel-parity partials; lo+hi summed in epilogue.
#define FW 22
#define FST 68
#define AST 68

__global__ __launch_bounds__(512, 1)
void dcn_kernel(const float* __restrict__ bdcn, float* __restrict__ out)
{
    extern __shared__ float sm[];
    float* sF = sm;                         // 22*22*68 = 32912 floats
    float* sA = sm + FW*FW*FST;             // 256*68   = 17408
    float* sW = sA + 256*AST;               // 64*64    = 4096

    const int tid = threadIdx.x;
    const int b   = blockIdx.z;
    const int y0  = blockIdx.y << 4;
    const int x0  = blockIdx.x << 4;

    // ---- stage feat window (zero-filled outside image) ----
    for (int i = tid; i < FW*FW*16; i += 512) {
        int px = i >> 4, cs = (i & 15) << 2;
        int row = px / FW, col = px - row*FW;
        int gy = y0 - 3 + row, gx = x0 - 3 + col;
        float4 v = make_float4(0.f, 0.f, 0.f, 0.f);
        if ((unsigned)gy < (unsigned)Hh && (unsigned)gx < (unsigned)Ww)
            v = *(const float4*)&g_feat[(((b*Hh + gy)*Ww + gx) << 6) + cs];
        *(float4*)&sF[px*FST + cs] = v;
    }

    // sampling role: 2 threads per pixel
    const int pl    = tid >> 1;           // 0..255 raster (r*16 + c)
    const int chalf = (tid & 1) << 5;     // 0 or 32
    const int ar = pl >> 4, ac = pl & 15;
    const int ay = y0 + ar, ax = x0 + ac;
    const float* __restrict__ omp = &g_offmod[(((b*Hh + ay)*Ww + ax)) << 5];

    // GEMM role: thread = 4 px (stride 64) x 8 contiguous oc
    const int pxq = tid & 63;
    const int ocg = tid >> 6;

    unsigned long long acc2[4][8];
    #pragma unroll
    for (int i = 0; i < 4; i++)
        #pragma unroll
        for (int j = 0; j < 8; j++) acc2[i][j] = 0ull;

    __syncthreads();

    for (int k = 0; k < 9; k++) {
        // load wdcn tap slice [c2][oc][2] (coalesced)
        #pragma unroll 4
        for (int i = tid; i < 4096; i += 512) sW[i] = g_wdcnt[(k << 12) + i];

        // ---- bilinear sample 32 channels into sA ----
        {
            float dy = omp[2*k], dxo = omp[2*k + 1], m = omp[18 + k];
            int ki = k/3 - 1, kj = k - (k/3)*3 - 1;
            float py  = (float)(ay + ki) + dy;
            float pxf = (float)(ax + kj) + dxo;
            float fy = floorf(py), fx = floorf(pxf);
            float wy = py - fy, wx = pxf - fx;
            int iy0 = (int)fy, ix0 = (int)fx;
            float w00 = m*(1.f-wy)*(1.f-wx), w01 = m*(1.f-wy)*wx;
            float w10 = m*wy*(1.f-wx),       w11 = m*wy*wx;
            float* dst = &sA[pl*AST + chalf];
            int ry = iy0 - y0 + 3, rx = ix0 - x0 + 3;
            if ((unsigned)ry <= (unsigned)(FW-2) && (unsigned)rx <= (unsigned)(FW-2)) {
                const float* base = &sF[(ry*FW + rx)*FST + chalf];
                const float4* q00 = (const float4*)base;
                const float4* q01 = (const float4*)(base + FST);
                const float4* q10 = (const float4*)(base + FW*FST);
                const float4* q11 = (const float4*)(base + FW*FST + FST);
                #pragma unroll
                for (int j = 0; j < 8; j++) {
                    float4 c00 = q00[j], c01 = q01[j], c10 = q10[j], c11 = q11[j];
                    float4 rv;
                    rv.x = w00*c00.x + w01*c01.x + w10*c10.x + w11*c11.x;
                    rv.y = w00*c00.y + w01*c01.y + w10*c10.y + w11*c11.y;
                    rv.z = w00*c00.z + w01*c01.z + w10*c10.z + w11*c11.z;
                    rv.w = w00*c00.w + w01*c01.w + w10*c10.w + w11*c11.w;
                    *(float4*)&dst[4*j] = rv;
                }
            } else {
                int iy1 = iy0 + 1, ix1 = ix0 + 1;
                bool vy0 = (iy0 >= 0) && (iy0 < Hh);
                bool vy1 = (iy1 >= 0) && (iy1 < Hh);
                bool vx0 = (ix0 >= 0) && (ix0 < Ww);
                bool vx1 = (ix1 >= 0) && (ix1 < Ww);
                float m00 = w00 * ((vy0 && vx0) ? 1.f : 0.f);
                float m01 = w01 * ((vy0 && vx1) ? 1.f : 0.f);
                float m10 = w10 * ((vy1 && vx0) ? 1.f : 0.f);
                float m11 = w11 * ((vy1 && vx1) ? 1.f : 0.f);
                int cy0 = min(max(iy0, 0), Hh-1), cx0 = min(max(ix0, 0), Ww-1);
                int cy1 = min(max(iy1, 0), Hh-1), cx1 = min(max(ix1, 0), Ww-1);
                const float4* p00 = (const float4*)&g_feat[(((b*Hh + cy0)*Ww + cx0) << 6) + chalf];
                const float4* p01 = (const float4*)&g_feat[(((b*Hh + cy0)*Ww + cx1) << 6) + chalf];
                const float4* p10 = (const float4*)&g_feat[(((b*Hh + cy1)*Ww + cx0) << 6) + chalf];
                const float4* p11 = (const float4*)&g_feat[(((b*Hh + cy1)*Ww + cx1) << 6) + chalf];
                #pragma unroll
                for (int j = 0; j < 8; j++) {
                    float4 c00 = p00[j], c01 = p01[j], c10 = p10[j], c11 = p11[j];
                    float4 rv;
                    rv.x = m00*c00.x + m01*c01.x + m10*c10.x + m11*c11.x;
                    rv.y = m00*c00.y + m01*c01.y + m10*c10.y + m11*c11.y;
                    rv.z = m00*c00.z + m01*c01.z + m10*c10.z + m11*c11.z;
                    rv.w = m00*c00.w + m01*c01.w + m10*c10.w + m11*c11.w;
                    *(float4*)&dst[4*j] = rv;
                }
            }
        }
        __syncthreads();

        // ---- GEMM: acc2[4px][8oc] += sA-pairs * sW-pairs over 32 channel pairs ----
        #pragma unroll 4
        for (int c2 = 0; c2 < 32; c2++) {
            unsigned long long a2[4];
            #pragma unroll
            for (int i = 0; i < 4; i++)
                a2[i] = *(const unsigned long long*)&sA[(pxq + 64*i)*AST + 2*c2];
            const float* wb = &sW[c2*128 + ocg*16];
            ulonglong2 wq0 = *(const ulonglong2*)(wb);        // oc j=0,1  (broadcast)
            ulonglong2 wq1 = *(const ulonglong2*)(wb + 4);    // j=2,3
            ulonglong2 wq2 = *(const ulonglong2*)(wb + 8);    // j=4,5
            ulonglong2 wq3 = *(const ulonglong2*)(wb + 12);   // j=6,7
            #pragma unroll
            for (int i = 0; i < 4; i++) {
                fma2(acc2[i][0], a2[i], wq0.x);
                fma2(acc2[i][1], a2[i], wq0.y);
                fma2(acc2[i][2], a2[i], wq1.x);
                fma2(acc2[i][3], a2[i], wq1.y);
                fma2(acc2[i][4], a2[i], wq2.x);
                fma2(acc2[i][5], a2[i], wq2.y);
                fma2(acc2[i][6], a2[i], wq3.x);
                fma2(acc2[i][7], a2[i], wq3.y);
            }
        }
        __syncthreads();
    }

    // ---- epilogue: sum parity halves, NCHW output ----
    #pragma unroll
    for (int j = 0; j < 8; j++) {
        int oc = ocg*8 + j;
        float bv = bdcn[oc];
        #pragma unroll
        for (int i = 0; i < 4; i++) {
            int p = pxq + 64*i;
            int row = p >> 4, col = p & 15;
            float2 v = unpack2(acc2[i][j]);
            out[((b*64 + oc)*Hh + y0 + row)*Ww + x0 + col] = v.x + v.y + bv;
        }
    }
}

// ---------------- launch ----------------
extern "C" void kernel_launch(void* const* d_in, const int* in_sizes, int n_in,
                              void* d_out, int out_size)
{
    const float* x_vq  = (const float*)d_in[0];
    const float* x_res = (const float*)d_in[1];
    const float* W1    = (const float*)d_in[2];
    const float* b1    = (const float*)d_in[3];
    const float* Woff  = (const float*)d_in[4];
    const float* boff  = (const float*)d_in[5];
    const float* Wmod  = (const float*)d_in[6];
    const float* bmod  = (const float*)d_in[7];
    const float* Wdcn  = (const float*)d_in[8];
    const float* bdcn  = (const float*)d_in[9];
    float* out = (float*)d_out;

    prep_kernel<<<(128*9*64 + 255)/256, 256>>>(W1, Woff, Wmod, Wdcn, boff, bmod);

    {
        dim3 grid(Ww/32, Hh/8, Bn);
        conv3x3_kernel<128, 64, 8, 0><<<grid, 256>>>(x_vq, x_res, b1);
    }
    {
        dim3 grid(Ww/32, Hh/8, Bn);
        conv3x3_kernel<64, 32, 4, 1><<<grid, 256>>>(nullptr, nullptr, nullptr);
    }
    {
        const int smem_bytes = (FW*FW*FST + 256*AST + 64*64) * (int)sizeof(float);
        cudaFuncSetAttribute(dcn_kernel, cudaFuncAttributeMaxDynamicSharedMemorySize, smem_bytes);
        dim3 grid(Ww/16, Hh/16, Bn);
        dcn_kernel<<<grid, 512, smem_bytes>>>(bdcn, out);
    }
}

// round 13
// speedup vs baseline: 1.4411x; 1.0503x over previous
#include <cuda_runtime.h>
#include <math.h>

#define Bn 8
#define Hh 128
#define Ww 128

// ---------------- f32x2 packed helpers ----------------
__device__ __forceinline__ unsigned long long pack2(float lo, float hi) {
    unsigned long long r;
    asm("mov.b64 %0, {%1, %2};" : "=l"(r) : "f"(lo), "f"(hi));
    return r;
}
__device__ __forceinline__ void fma2(unsigned long long& acc,
                                     unsigned long long a, unsigned long long b) {
    asm("fma.rn.f32x2 %0, %1, %2, %0;" : "+l"(acc) : "l"(a), "l"(b));
}
__device__ __forceinline__ float2 unpack2(unsigned long long v) {
    float2 r;
    asm("mov.b64 {%0, %1}, %2;" : "=f"(r.x), "=f"(r.y) : "l"(v));
    return r;
}

// ---------------- device scratch ----------------
__device__ float g_feat[Bn*Hh*Ww*64];      // NHWC feat
__device__ float g_offmod[Bn*Hh*Ww*32];    // NHWC off(18)+mod(9)
__device__ float g_w1t[128*9*64];          // [ic][tap][oc]
__device__ float g_w2t[64*9*32];           // [ic][tap][oc32]
__device__ float g_wdcnt[9*32*64*2];       // [tap][c2][oc][parity]
__device__ float g_b2[32];

// ---------------- weight transpose / merge ----------------
__global__ void prep_kernel(const float* __restrict__ W1,
                            const float* __restrict__ Woff,
                            const float* __restrict__ Wmod,
                            const float* __restrict__ Wdcn,
                            const float* __restrict__ boff,
                            const float* __restrict__ bmod)
{
    int i = blockIdx.x * blockDim.x + threadIdx.x;
    if (i < 128*9*64) {                  // W1 [oc][ic][9] -> [ic][t][oc]
        int ic = i / 576; int rem = i - ic*576;
        int t = rem / 64; int oc = rem & 63;
        g_w1t[i] = W1[(oc*128 + ic)*9 + t];
    }
    if (i < 64*9*32) {                   // Woff(18)+Wmod(9)+pad -> [ic][t][oc32]
        int ic = i / 288; int rem = i - ic*288;
        int t = rem >> 5; int oc = rem & 31;
        float v = 0.f;
        if (oc < 18)      v = Woff[(oc*64 + ic)*9 + t];
        else if (oc < 27) v = Wmod[((oc-18)*64 + ic)*9 + t];
        g_w2t[i] = v;
    }
    if (i < 9*64*64) {                   // Wdcn [oc][c][9] -> [tap][c2][oc][par]
        int k = i >> 12;
        int r = i & 4095;
        int c2  = r >> 7;
        int oc  = (r >> 1) & 63;
        int par = i & 1;
        int c = c2*2 + par;
        g_wdcnt[i] = Wdcn[(oc*64 + c)*9 + k];
    }
    if (i < 32) g_b2[i] = (i < 18) ? boff[i] : (i < 27 ? bmod[i-18] : 0.f);
}

// ---------------- generic fused 3x3 conv (f32x2 inner) ----------------
// Tile: 8 rows x 32 cols, all OC. 256 threads; thread = OCPT oc x 8 px.
// Weights [ic][tap][oc]: adjacent oc form natural f32x2 pairs (broadcast LDS.64).
template<int IC, int OC, int OCPT, int MODE>
__global__ __launch_bounds__(256)
void conv3x3_kernel(const float* __restrict__ in0,
                    const float* __restrict__ in1,
                    const float* __restrict__ bias1)
{
    constexpr int OCG = OC / OCPT;
    constexpr int NT  = OCG * 32;      // 256
    constexpr int ICB = 8;
    constexpr int RS  = 36;            // padded smem row stride
    constexpr int JP  = OCPT / 2;      // oc pairs per thread

    __shared__ __align__(16) float sIn[ICB][10*RS];
    __shared__ __align__(16) float sW[ICB][9*OC];

    const float* __restrict__ wT   = (MODE == 0) ? g_w1t : g_w2t;
    const float* __restrict__ bias = (MODE == 0) ? bias1 : g_b2;

    const int tid  = threadIdx.x;
    const int b    = blockIdx.z;
    const int y0   = blockIdx.y << 3;
    const int x0   = blockIdx.x << 5;
    const int ocg  = tid >> 5;
    const int lane = tid & 31;
    const int r    = lane >> 2;
    const int xb   = (lane & 3) << 3;

    unsigned long long acc2[JP][8];
    #pragma unroll
    for (int j2 = 0; j2 < JP; j2++) {
        int oc0 = ocg*OCPT + 2*j2;
        unsigned long long bv = pack2(bias[oc0], bias[oc0+1]);
        #pragma unroll
        for (int p = 0; p < 8; p++) acc2[j2][p] = bv;
    }

    for (int ic0 = 0; ic0 < IC; ic0 += ICB) {
        __syncthreads();
        for (int i = tid; i < ICB*340; i += NT) {
            int icL = i / 340; int rem = i - icL*340;
            int rr = rem / 34; int cc = rem - rr*34;
            int gy = y0 - 1 + rr, gx = x0 - 1 + cc;
            float v = 0.f;
            if ((unsigned)gy < (unsigned)Hh && (unsigned)gx < (unsigned)Ww) {
                int ic = ic0 + icL;
                if (MODE == 0) {
                    const float* src = (ic < 64) ? in0 : in1;
                    v = src[((b*64 + (ic & 63))*Hh + gy)*Ww + gx];
                } else {
                    v = g_feat[(((b*Hh + gy)*Ww + gx) << 6) + ic];
                }
            }
            sIn[icL][rr*RS + cc] = v;
        }
        for (int i = tid; i < ICB*9*OC; i += NT) {
            int icL = i / (9*OC); int j = i - icL*(9*OC);
            sW[icL][j] = wT[(ic0 + icL)*(9*OC) + j];
        }
        __syncthreads();

        #pragma unroll
        for (int icL = 0; icL < ICB; icL++) {
            #pragma unroll
            for (int dy = 0; dy < 3; dy++) {
                int base = (r + dy)*RS + xb;
                float4 a4 = *(const float4*)&sIn[icL][base];
                float4 b4 = *(const float4*)&sIn[icL][base + 4];
                float v8 = sIn[icL][base + 8];
                float v9 = sIn[icL][base + 9];
                unsigned long long vb[10];
                vb[0] = pack2(a4.x, a4.x); vb[1] = pack2(a4.y, a4.y);
                vb[2] = pack2(a4.z, a4.z); vb[3] = pack2(a4.w, a4.w);
                vb[4] = pack2(b4.x, b4.x); vb[5] = pack2(b4.y, b4.y);
                vb[6] = pack2(b4.z, b4.z); vb[7] = pack2(b4.w, b4.w);
                vb[8] = pack2(v8, v8);     vb[9] = pack2(v9, v9);
                #pragma unroll
                for (int dx = 0; dx < 3; dx++) {
                    int t = dy*3 + dx;
                    unsigned long long w2[JP];
                    #pragma unroll
                    for (int j2 = 0; j2 < JP; j2++)
                        w2[j2] = *(const unsigned long long*)
                                 &sW[icL][t*OC + ocg*OCPT + 2*j2];   // broadcast
                    #pragma unroll
                    for (int p = 0; p < 8; p++) {
                        #pragma unroll
                        for (int j2 = 0; j2 < JP; j2++)
                            fma2(acc2[j2][p], vb[p+dx], w2[j2]);
                    }
                }
            }
        }
    }

    const int y = y0 + r;
    #pragma unroll
    for (int j2 = 0; j2 < JP; j2++) {
        int oc0 = ocg*OCPT + 2*j2;
        #pragma unroll
        for (int p = 0; p < 8; p++) {
            int x = x0 + xb + p;
            float2 v = unpack2(acc2[j2][p]);
            if (MODE == 0) {
                float* dst = &g_feat[(((b*Hh + y)*Ww + x) << 6)];
                dst[oc0]     = v.x;
                dst[oc0 + 1] = v.y;
            } else {
                float* dst = &g_offmod[(((b*Hh + y)*Ww + x) << 5)];
                if (oc0 < 27) {
                    float a = v.x;
                    if (oc0 >= 18) a = 2.f / (1.f + expf(-a));
                    dst[oc0] = a;
                }
                if (oc0 + 1 < 27) {
                    float a = v.y;
                    if (oc0 + 1 >= 18) a = 2.f / (1.f + expf(-a));
                    dst[oc0 + 1] = a;
                }
            }
        }
    }
}

// ---------------- deformable sampling + DCN GEMM (smem-staged, f32x2) ----------------
// Block: 16x16 px tile, 64 oc, 512 threads.
// sF: staged feat window 22x22 (halo ±3), ch stride 68.
// sA: sampled [256 px][68].  sW: [c2][oc][2] tap slice (channel-parity pairs).
// GEMM: pxq = tid&63, ocg = tid>>6 (warp-uniform -> weight broadcast).
// A loaded as ulonglong2 (2 channel-pairs per LDS.128); chunk = 4 channels.
#define FW 22
#define FST 68
#define AST 68

__global__ __launch_bounds__(512, 1)
void dcn_kernel(const float* __restrict__ bdcn, float* __restrict__ out)
{
    extern __shared__ float sm[];
    float* sF = sm;                         // 22*22*68 = 32912 floats
    float* sA = sm + FW*FW*FST;             // 256*68   = 17408
    float* sW = sA + 256*AST;               // 64*64    = 4096

    const int tid = threadIdx.x;
    const int b   = blockIdx.z;
    const int y0  = blockIdx.y << 4;
    const int x0  = blockIdx.x << 4;

    // ---- stage feat window (zero-filled outside image) ----
    for (int i = tid; i < FW*FW*16; i += 512) {
        int px = i >> 4, cs = (i & 15) << 2;
        int row = px / FW, col = px - row*FW;
        int gy = y0 - 3 + row, gx = x0 - 3 + col;
        float4 v = make_float4(0.f, 0.f, 0.f, 0.f);
        if ((unsigned)gy < (unsigned)Hh && (unsigned)gx < (unsigned)Ww)
            v = *(const float4*)&g_feat[(((b*Hh + gy)*Ww + gx) << 6) + cs];
        *(float4*)&sF[px*FST + cs] = v;
    }

    // sampling role: 2 threads per pixel
    const int pl    = tid >> 1;           // 0..255 raster (r*16 + c)
    const int chalf = (tid & 1) << 5;     // 0 or 32
    const int ar = pl >> 4, ac = pl & 15;
    const int ay = y0 + ar, ax = x0 + ac;
    const float* __restrict__ omp = &g_offmod[(((b*Hh + ay)*Ww + ax)) << 5];

    // GEMM role: thread = 4 px (stride 64) x 8 contiguous oc
    const int pxq = tid & 63;
    const int ocg = tid >> 6;

    unsigned long long acc2[4][8];
    #pragma unroll
    for (int i = 0; i < 4; i++)
        #pragma unroll
        for (int j = 0; j < 8; j++) acc2[i][j] = 0ull;

    __syncthreads();

    for (int k = 0; k < 9; k++) {
        // load wdcn tap slice [c2][oc][2] (coalesced)
        #pragma unroll 4
        for (int i = tid; i < 4096; i += 512) sW[i] = g_wdcnt[(k << 12) + i];

        // ---- bilinear sample 32 channels into sA ----
        {
            float dy = omp[2*k], dxo = omp[2*k + 1], m = omp[18 + k];
            int ki = k/3 - 1, kj = k - (k/3)*3 - 1;
            float py  = (float)(ay + ki) + dy;
            float pxf = (float)(ax + kj) + dxo;
            float fy = floorf(py), fx = floorf(pxf);
            float wy = py - fy, wx = pxf - fx;
            int iy0 = (int)fy, ix0 = (int)fx;
            float w00 = m*(1.f-wy)*(1.f-wx), w01 = m*(1.f-wy)*wx;
            float w10 = m*wy*(1.f-wx),       w11 = m*wy*wx;
            float* dst = &sA[pl*AST + chalf];
            int ry = iy0 - y0 + 3, rx = ix0 - x0 + 3;
            if ((unsigned)ry <= (unsigned)(FW-2) && (unsigned)rx <= (unsigned)(FW-2)) {
                const float* base = &sF[(ry*FW + rx)*FST + chalf];
                const float4* q00 = (const float4*)base;
                const float4* q01 = (const float4*)(base + FST);
                const float4* q10 = (const float4*)(base + FW*FST);
                const float4* q11 = (const float4*)(base + FW*FST + FST);
                #pragma unroll
                for (int j = 0; j < 8; j++) {
                    float4 c00 = q00[j], c01 = q01[j], c10 = q10[j], c11 = q11[j];
                    float4 rv;
                    rv.x = w00*c00.x + w01*c01.x + w10*c10.x + w11*c11.x;
                    rv.y = w00*c00.y + w01*c01.y + w10*c10.y + w11*c11.y;
                    rv.z = w00*c00.z + w01*c01.z + w10*c10.z + w11*c11.z;
                    rv.w = w00*c00.w + w01*c01.w + w10*c10.w + w11*c11.w;
                    *(float4*)&dst[4*j] = rv;
                }
            } else {
                int iy1 = iy0 + 1, ix1 = ix0 + 1;
                bool vy0 = (iy0 >= 0) && (iy0 < Hh);
                bool vy1 = (iy1 >= 0) && (iy1 < Hh);
                bool vx0 = (ix0 >= 0) && (ix0 < Ww);
                bool vx1 = (ix1 >= 0) && (ix1 < Ww);
                float m00 = w00 * ((vy0 && vx0) ? 1.f : 0.f);
                float m01 = w01 * ((vy0 && vx1) ? 1.f : 0.f);
                float m10 = w10 * ((vy1 && vx0) ? 1.f : 0.f);
                float m11 = w11 * ((vy1 && vx1) ? 1.f : 0.f);
                int cy0 = min(max(iy0, 0), Hh-1), cx0 = min(max(ix0, 0), Ww-1);
                int cy1 = min(max(iy1, 0), Hh-1), cx1 = min(max(ix1, 0), Ww-1);
                const float4* p00 = (const float4*)&g_feat[(((b*Hh + cy0)*Ww + cx0) << 6) + chalf];
                const float4* p01 = (const float4*)&g_feat[(((b*Hh + cy0)*Ww + cx1) << 6) + chalf];
                const float4* p10 = (const float4*)&g_feat[(((b*Hh + cy1)*Ww + cx0) << 6) + chalf];
                const float4* p11 = (const float4*)&g_feat[(((b*Hh + cy1)*Ww + cx1) << 6) + chalf];
                #pragma unroll
                for (int j = 0; j < 8; j++) {
                    float4 c00 = p00[j], c01 = p01[j], c10 = p10[j], c11 = p11[j];
                    float4 rv;
                    rv.x = m00*c00.x + m01*c01.x + m10*c10.x + m11*c11.x;
                    rv.y = m00*c00.y + m01*c01.y + m10*c10.y + m11*c11.y;
                    rv.z = m00*c00.z + m01*c01.z + m10*c10.z + m11*c11.z;
                    rv.w = m00*c00.w + m01*c01.w + m10*c10.w + m11*c11.w;
                    *(float4*)&dst[4*j] = rv;
                }
            }
        }
        __syncthreads();

        // ---- GEMM: acc2[4px][8oc] += A-pairs * W-pairs, chunk = 4 channels ----
        #pragma unroll 8
        for (int c2 = 0; c2 < 32; c2 += 2) {
            // A: 2 channel-pairs per pixel via one LDS.128
            ulonglong2 aq[4];
            #pragma unroll
            for (int i = 0; i < 4; i++)
                aq[i] = *(const ulonglong2*)&sA[(pxq + 64*i)*AST + 2*c2];
            const float* wb0 = &sW[c2*128 + ocg*16];         // row c2 (pair lo)
            const float* wb1 = wb0 + 128;                    // row c2+1 (pair hi)
            #pragma unroll
            for (int h = 0; h < 2; h++) {                    // oc halves: j = 4h..4h+3
                ulonglong2 w0a = *(const ulonglong2*)(wb0 + 8*h);      // oc 4h,4h+1
                ulonglong2 w0b = *(const ulonglong2*)(wb0 + 8*h + 4);  // oc 4h+2,4h+3
                ulonglong2 w1a = *(const ulonglong2*)(wb1 + 8*h);
                ulonglong2 w1b = *(const ulonglong2*)(wb1 + 8*h + 4);
                #pragma unroll
                for (int i = 0; i < 4; i++) {
                    fma2(acc2[i][4*h+0], aq[i].x, w0a.x);
                    fma2(acc2[i][4*h+1], aq[i].x, w0a.y);
                    fma2(acc2[i][4*h+2], aq[i].x, w0b.x);
                    fma2(acc2[i][4*h+3], aq[i].x, w0b.y);
                    fma2(acc2[i][4*h+0], aq[i].y, w1a.x);
                    fma2(acc2[i][4*h+1], aq[i].y, w1a.y);
                    fma2(acc2[i][4*h+2], aq[i].y, w1b.x);
                    fma2(acc2[i][4*h+3], aq[i].y, w1b.y);
                }
            }
        }
        __syncthreads();
    }

    // ---- epilogue: sum parity halves, NCHW output ----
    #pragma unroll
    for (int j = 0; j < 8; j++) {
        int oc = ocg*8 + j;
        float bv = bdcn[oc];
        #pragma unroll
        for (int i = 0; i < 4; i++) {
            int p = pxq + 64*i;
            int row = p >> 4, col = p & 15;
            float2 v = unpack2(acc2[i][j]);
            out[((b*64 + oc)*Hh + y0 + row)*Ww + x0 + col] = v.x + v.y + bv;
        }
    }
}

// ---------------- launch ----------------
extern "C" void kernel_launch(void* const* d_in, const int* in_sizes, int n_in,
                              void* d_out, int out_size)
{
    const float* x_vq  = (const float*)d_in[0];
    const float* x_res = (const float*)d_in[1];
    const float* W1    = (const float*)d_in[2];
    const float* b1    = (const float*)d_in[3];
    const float* Woff  = (const float*)d_in[4];
    const float* boff  = (const float*)d_in[5];
    const float* Wmod  = (const float*)d_in[6];
    const float* bmod  = (const float*)d_in[7];
    const float* Wdcn  = (const float*)d_in[8];
    const float* bdcn  = (const float*)d_in[9];
    float* out = (float*)d_out;

    prep_kernel<<<(128*9*64 + 255)/256, 256>>>(W1, Woff, Wmod, Wdcn, boff, bmod);

    {
        dim3 grid(Ww/32, Hh/8, Bn);
        conv3x3_kernel<128, 64, 8, 0><<<grid, 256>>>(x_vq, x_res, b1);
    }
    {
        dim3 grid(Ww/32, Hh/8, Bn);
        conv3x3_kernel<64, 32, 4, 1><<<grid, 256>>>(nullptr, nullptr, nullptr);
    }
    {
        const int smem_bytes = (FW*FW*FST + 256*AST + 64*64) * (int)sizeof(float);
        cudaFuncSetAttribute(dcn_kernel, cudaFuncAttributeMaxDynamicSharedMemorySize, smem_bytes);
        dim3 grid(Ww/16, Hh/16, Bn);
        dcn_kernel<<<grid, 512, smem_bytes>>>(bdcn, out);
    }
}